// round 2
// baseline (speedup 1.0000x reference)
#include <cuda_runtime.h>
#include <cuda_bf16.h>
#include <math.h>

#define Bq 128
#define Sq 4096
#define Hq 512
#define Vq 32000

// ---------------- scratch (no allocations allowed) ----------------
__device__ float g_x[Bq * 4 * Hq];            // GRU input  [B,4H]
__device__ float g_gx[Bq * 3 * Hq];           // x @ W_ih^T
__device__ float g_gh[Bq * 3 * Hq];           // h @ W_hh^T
__device__ float g_hnew[Bq * Hq];
__device__ float g_scores[Bq * Sq];
__device__ float g_attn[Bq * Sq];
__device__ float g_ctx_part[32 * Bq * Hq];    // context partials over 32 s-chunks
__device__ float g_concat_in[Bq * 2 * Hq];    // [h_new | context]
__device__ float g_concat_out[Bq * Hq];
__device__ float g_gemm_part[8 * Bq * 3 * Hq];// split-K partials (max 8*128*1536)

// ---------------- embedding gather ----------------
__global__ void embed_kernel(const int* __restrict__ seq, const int* __restrict__ pos,
                             const int* __restrict__ yr, const int* __restrict__ fr,
                             const float* __restrict__ et, const float* __restrict__ ep,
                             const float* __restrict__ ey, const float* __restrict__ ei)
{
    int idx = blockIdx.x * 256 + threadIdx.x;      // over B*4H/4 = 65536 float4
    int b = idx >> 9;                               // / (4H/4 = 512)
    int c = idx & 511;                              // float4 column
    int region = c >> 7;                            // /128 (H/4)
    int off = c & 127;
    const float* tbl; int r;
    if (region == 0)      { tbl = et; r = seq[b]; }
    else if (region == 1) { tbl = ep; r = pos[b]; }
    else if (region == 2) { tbl = ey; r = yr[b]; }
    else                  { tbl = ei; r = fr[b]; }
    float4 v = ((const float4*)(tbl + (size_t)r * Hq))[off];
    ((float4*)g_x)[idx] = v;
}

// ---------------- 128x128 tiled SGEMM: C[M=128,N] = A[128,K] @ W[N,K]^T ----------------
// grid (N/128, kSplit). kSplit>1 -> write partials; else bias+act epilogue.
#define BKq 16
__global__ __launch_bounds__(256, 2)
void gemm128(const float* __restrict__ A, int K,
             const float* __restrict__ W,
             const float* __restrict__ bias,
             float* __restrict__ C, int N,
             float* __restrict__ Cpart, int act)
{
    __shared__ float As[BKq][132];
    __shared__ float Ws[BKq][132];
    int t = threadIdx.x;
    int nblk = blockIdx.x * 128;
    int ksplit = gridDim.y;
    int klen = K / ksplit;
    int k0 = blockIdx.y * klen;
    int tm = (t >> 4) * 8;
    int tn = (t & 15) * 8;

    float acc[8][8];
#pragma unroll
    for (int i = 0; i < 8; i++)
#pragma unroll
        for (int j = 0; j < 8; j++) acc[i][j] = 0.f;

    for (int kk = k0; kk < k0 + klen; kk += BKq) {
#pragma unroll
        for (int i = 0; i < 2; i++) {
            int idx = t + i * 256;           // 0..511
            int row = idx >> 2;
            int c4 = idx & 3;
            float4 v = *(const float4*)(A + (size_t)row * K + kk + c4 * 4);
            As[c4 * 4 + 0][row] = v.x;
            As[c4 * 4 + 1][row] = v.y;
            As[c4 * 4 + 2][row] = v.z;
            As[c4 * 4 + 3][row] = v.w;
        }
#pragma unroll
        for (int i = 0; i < 2; i++) {
            int idx = t + i * 256;
            int row = idx >> 2;
            int c4 = idx & 3;
            float4 v = *(const float4*)(W + (size_t)(nblk + row) * K + kk + c4 * 4);
            Ws[c4 * 4 + 0][row] = v.x;
            Ws[c4 * 4 + 1][row] = v.y;
            Ws[c4 * 4 + 2][row] = v.z;
            Ws[c4 * 4 + 3][row] = v.w;
        }
        __syncthreads();
#pragma unroll
        for (int k = 0; k < BKq; ++k) {
            float4 a0 = *(const float4*)&As[k][tm];
            float4 a1 = *(const float4*)&As[k][tm + 4];
            float4 b0 = *(const float4*)&Ws[k][tn];
            float4 b1 = *(const float4*)&Ws[k][tn + 4];
            float av[8] = {a0.x, a0.y, a0.z, a0.w, a1.x, a1.y, a1.z, a1.w};
            float bv[8] = {b0.x, b0.y, b0.z, b0.w, b1.x, b1.y, b1.z, b1.w};
#pragma unroll
            for (int i = 0; i < 8; i++)
#pragma unroll
                for (int j = 0; j < 8; j++)
                    acc[i][j] += av[i] * bv[j];
        }
        __syncthreads();
    }

    if (ksplit > 1) {
        float* P = Cpart + (size_t)blockIdx.y * 128 * N;
#pragma unroll
        for (int i = 0; i < 8; i++) {
            float* row = P + (size_t)(tm + i) * N + nblk + tn;
            *(float4*)(row)     = make_float4(acc[i][0], acc[i][1], acc[i][2], acc[i][3]);
            *(float4*)(row + 4) = make_float4(acc[i][4], acc[i][5], acc[i][6], acc[i][7]);
        }
    } else {
#pragma unroll
        for (int i = 0; i < 8; i++) {
            float* row = C + (size_t)(tm + i) * N + nblk + tn;
#pragma unroll
            for (int j = 0; j < 8; j++) {
                float c = acc[i][j] + (bias ? bias[nblk + tn + j] : 0.f);
                if (act == 1) c = tanhf(c);
                row[j] = c;
            }
        }
    }
}

__global__ void reduce_split(const float* __restrict__ part, const float* __restrict__ bias,
                             float* __restrict__ C, int total, int N, int ksplit, int act)
{
    int idx = blockIdx.x * 256 + threadIdx.x;
    if (idx >= total) return;
    float s = 0.f;
    for (int z = 0; z < ksplit; z++) s += part[(size_t)z * total + idx];
    s += bias[idx % N];
    if (act == 1) s = tanhf(s);
    C[idx] = s;
}

// ---------------- GRU gates ----------------
__global__ void gate_kernel(const float* __restrict__ hprev, float* __restrict__ out_h)
{
    int idx = blockIdx.x * 256 + threadIdx.x;   // B*H
    int b = idx >> 9;                            // /H
    int j = idx & 511;
    const float* gx = g_gx + (size_t)b * 3 * Hq;
    const float* gh = g_gh + (size_t)b * 3 * Hq;
    float r = 1.f / (1.f + __expf(-(gx[j] + gh[j])));
    float z = 1.f / (1.f + __expf(-(gx[Hq + j] + gh[Hq + j])));
    float n = tanhf(gx[2 * Hq + j] + r * gh[2 * Hq + j]);
    float hn = (1.f - z) * n + z * hprev[idx];
    g_hnew[idx] = hn;
    g_concat_in[(size_t)b * 2 * Hq + j] = hn;
    if (out_h) out_h[idx] = hn;
}

// ---------------- attention scores: scores[b,s] = dot(h_new[b], enc[s,b,:]) ----------------
__global__ void scores_kernel(const float* __restrict__ enc)
{
    __shared__ float hs[Hq];
    int b = blockIdx.y;
    int t = threadIdx.x;
    hs[t] = g_hnew[(size_t)b * Hq + t];
    hs[t + 256] = g_hnew[(size_t)b * Hq + t + 256];
    __syncthreads();
    int w = t >> 5;
    int lane = t & 31;
    int s = blockIdx.x * 8 + w;
    const float4* e4 = (const float4*)(enc + ((size_t)s * Bq + b) * Hq);
    const float4* h4 = (const float4*)hs;
    float sum = 0.f;
#pragma unroll
    for (int i = 0; i < 4; i++) {
        float4 e = e4[lane + i * 32];
        float4 h = h4[lane + i * 32];
        sum += e.x * h.x + e.y * h.y + e.z * h.z + e.w * h.w;
    }
#pragma unroll
    for (int off = 16; off > 0; off >>= 1)
        sum += __shfl_down_sync(0xffffffffu, sum, off);
    if (lane == 0) g_scores[(size_t)b * Sq + s] = sum;
}

// ---------------- softmax over S per row ----------------
__global__ void softmax_kernel(float* __restrict__ out_attn)
{
    __shared__ float buf[Sq];
    __shared__ float red[256];
    int b = blockIdx.x;
    int t = threadIdx.x;
    float m = -1e30f;
    for (int i = t; i < Sq; i += 256) {
        float v = g_scores[(size_t)b * Sq + i];
        buf[i] = v;
        m = fmaxf(m, v);
    }
    red[t] = m; __syncthreads();
    for (int off = 128; off > 0; off >>= 1) {
        if (t < off) red[t] = fmaxf(red[t], red[t + off]);
        __syncthreads();
    }
    float mx = red[0]; __syncthreads();
    float sum = 0.f;
    for (int i = t; i < Sq; i += 256) {
        float e = __expf(buf[i] - mx);
        buf[i] = e;
        sum += e;
    }
    red[t] = sum; __syncthreads();
    for (int off = 128; off > 0; off >>= 1) {
        if (t < off) red[t] += red[t + off];
        __syncthreads();
    }
    float inv = 1.f / red[0];
    for (int i = t; i < Sq; i += 256) {
        float w = buf[i] * inv;
        g_attn[(size_t)b * Sq + i] = w;
        if (out_attn) out_attn[(size_t)b * Sq + i] = w;
    }
}

// ---------------- context partials: 32 s-chunks x B ----------------
__global__ void ctx_partial_kernel(const float* __restrict__ enc)
{
    int chunk = blockIdx.x;
    int b = blockIdx.y;
    int t = threadIdx.x;    // 128 threads, each a float4 of H
    const float* wrow = g_attn + (size_t)b * Sq + chunk * 128;
    float4 acc = make_float4(0.f, 0.f, 0.f, 0.f);
#pragma unroll 4
    for (int s = 0; s < 128; s++) {
        float w = wrow[s];
        const float4* e4 = (const float4*)(enc + ((size_t)(chunk * 128 + s) * Bq + b) * Hq);
        float4 e = e4[t];
        acc.x += w * e.x; acc.y += w * e.y; acc.z += w * e.z; acc.w += w * e.w;
    }
    ((float4*)g_ctx_part)[((size_t)chunk * Bq + b) * 128 + t] = acc;
}

__global__ void ctx_reduce_kernel()
{
    int idx = blockIdx.x * 256 + threadIdx.x;   // B*H
    int b = idx >> 9;
    int h = idx & 511;
    float s = 0.f;
#pragma unroll
    for (int c = 0; c < 32; c++)
        s += g_ctx_part[((size_t)c * Bq + b) * Hq + h];
    g_concat_in[(size_t)b * 2 * Hq + Hq + h] = s;
}

// ---------------- launch ----------------
extern "C" void kernel_launch(void* const* d_in, const int* in_sizes, int n_in,
                              void* d_out, int out_size)
{
    const int* input_seq   = (const int*)d_in[0];
    const int* positions   = (const int*)d_in[1];
    const int* years       = (const int*)d_in[2];
    const int* froms       = (const int*)d_in[3];
    const float* last_h    = (const float*)d_in[4];
    const float* enc       = (const float*)d_in[5];
    const float* emb_tok   = (const float*)d_in[6];
    const float* emb_pos   = (const float*)d_in[7];
    const float* emb_year  = (const float*)d_in[8];
    const float* emb_inst  = (const float*)d_in[9];
    const float* W_ih      = (const float*)d_in[10];
    const float* b_ih      = (const float*)d_in[11];
    const float* W_hh      = (const float*)d_in[12];
    const float* b_hh      = (const float*)d_in[13];
    const float* W_concat  = (const float*)d_in[14];
    const float* b_concat  = (const float*)d_in[15];
    const float* W_out     = (const float*)d_in[16];
    const float* b_out     = (const float*)d_in[17];

    float* out = (float*)d_out;
    float* out_logits = out;
    float* out_h = nullptr;
    float* out_attn = nullptr;
    long long need = (long long)Bq * Vq + (long long)Bq * Hq + (long long)Bq * Sq;
    if ((long long)out_size >= need) {
        out_h = out + (size_t)Bq * Vq;
        out_attn = out_h + (size_t)Bq * Hq;
    }

    float *gx, *gh, *xbuf, *part, *concat_in, *concat_out;
    cudaGetSymbolAddress((void**)&gx, g_gx);
    cudaGetSymbolAddress((void**)&gh, g_gh);
    cudaGetSymbolAddress((void**)&xbuf, g_x);
    cudaGetSymbolAddress((void**)&part, g_gemm_part);
    cudaGetSymbolAddress((void**)&concat_in, g_concat_in);
    cudaGetSymbolAddress((void**)&concat_out, g_concat_out);

    // 1. embeddings -> x [B,4H]
    embed_kernel<<<256, 256>>>(input_seq, positions, years, froms,
                               emb_tok, emb_pos, emb_year, emb_inst);
    // 2. gx = x @ W_ih^T + b_ih   (split-K 8)
    gemm128<<<dim3(12, 8), 256>>>(xbuf, 4 * Hq, W_ih, nullptr, nullptr, 3 * Hq, part, 0);
    reduce_split<<<(Bq * 3 * Hq + 255) / 256, 256>>>(part, b_ih, gx, Bq * 3 * Hq, 3 * Hq, 8, 0);
    // 3. gh = h @ W_hh^T + b_hh   (split-K 4)
    gemm128<<<dim3(12, 4), 256>>>(last_h, Hq, W_hh, nullptr, nullptr, 3 * Hq, part, 0);
    reduce_split<<<(Bq * 3 * Hq + 255) / 256, 256>>>(part, b_hh, gh, Bq * 3 * Hq, 3 * Hq, 4, 0);
    // 4. gates -> h_new
    gate_kernel<<<(Bq * Hq) / 256, 256>>>(last_h, out_h);
    // 5. attention scores
    scores_kernel<<<dim3(Sq / 8, Bq), 256>>>(enc);
    // 6. softmax -> attn weights
    softmax_kernel<<<Bq, 256>>>(out_attn);
    // 7. context partials + reduce -> concat_in[:, H:2H]
    ctx_partial_kernel<<<dim3(32, Bq), 128>>>(enc);
    ctx_reduce_kernel<<<(Bq * Hq) / 256, 256>>>();
    // 8. concat_out = tanh(concat_in @ W_concat^T + b_concat) (split-K 8, tanh in reduce)
    gemm128<<<dim3(4, 8), 256>>>(concat_in, 2 * Hq, W_concat, nullptr, nullptr, Hq, part, 0);
    reduce_split<<<(Bq * Hq + 255) / 256, 256>>>(part, b_concat, concat_out, Bq * Hq, Hq, 8, 1);
    // 9. logits = concat_out @ W_out^T + b_out
    gemm128<<<dim3(Vq / 128, 1), 256>>>(concat_out, Hq, W_out, b_out, out_logits, Vq, nullptr, 0);
}

// round 3
// speedup vs baseline: 1.2636x; 1.2636x over previous
#include <cuda_runtime.h>
#include <cuda_bf16.h>
#include <math.h>

#define Bq 128
#define Sq 4096
#define Hq 512
#define Vq 32000
#define NCHUNK 64            // S split into 64 chunks of 64 for online softmax partials

// ---------------- scratch (no allocations allowed) ----------------
__device__ float g_x[Bq * 4 * Hq];            // GRU input  [B,4H]
__device__ float g_gx[Bq * 3 * Hq];           // x @ W_ih^T
__device__ float g_gh[Bq * 3 * Hq];           // h @ W_hh^T
__device__ float g_hnew[Bq * Hq];
__device__ float g_scores[Bq * Sq];
__device__ float g_pm[Bq * NCHUNK];           // per-chunk running max
__device__ float g_pz[Bq * NCHUNK];           // per-chunk running sum
__device__ float g_pctx[Bq * NCHUNK * Hq];    // per-chunk weighted-ctx partial
__device__ float g_M[Bq];                     // final max per row
__device__ float g_Zinv[Bq];                  // final 1/Z per row
__device__ float g_concat_in[Bq * 2 * Hq];    // [h_new | context]
__device__ float g_concat_out[Bq * Hq];
__device__ float g_gemm_part[4 * Bq * Vq];    // split-K partials (vocab is the biggest user)

// ---------------- embedding gather ----------------
__global__ void embed_kernel(const int* __restrict__ seq, const int* __restrict__ pos,
                             const int* __restrict__ yr, const int* __restrict__ fr,
                             const float* __restrict__ et, const float* __restrict__ ep,
                             const float* __restrict__ ey, const float* __restrict__ ei)
{
    int idx = blockIdx.x * 256 + threadIdx.x;      // over B*4H/4 = 65536 float4
    int b = idx >> 9;
    int c = idx & 511;
    int region = c >> 7;
    int off = c & 127;
    const float* tbl; int r;
    if (region == 0)      { tbl = et; r = seq[b]; }
    else if (region == 1) { tbl = ep; r = pos[b]; }
    else if (region == 2) { tbl = ey; r = yr[b]; }
    else                  { tbl = ei; r = fr[b]; }
    float4 v = ((const float4*)(tbl + (size_t)r * Hq))[off];
    ((float4*)g_x)[idx] = v;
}

// ---------------- 128x128 tiled SGEMM: C[M=128,N] = A[128,K] @ W[N,K]^T ----------------
#define BKq 16
__global__ __launch_bounds__(256, 2)
void gemm128(const float* __restrict__ A, int K,
             const float* __restrict__ W,
             const float* __restrict__ bias,
             float* __restrict__ C, int N,
             float* __restrict__ Cpart, int act)
{
    __shared__ float As[BKq][132];
    __shared__ float Ws[BKq][132];
    int t = threadIdx.x;
    int nblk = blockIdx.x * 128;
    int ksplit = gridDim.y;
    int klen = K / ksplit;
    int k0 = blockIdx.y * klen;
    int tm = (t >> 4) * 8;
    int tn = (t & 15) * 8;

    float acc[8][8];
#pragma unroll
    for (int i = 0; i < 8; i++)
#pragma unroll
        for (int j = 0; j < 8; j++) acc[i][j] = 0.f;

    for (int kk = k0; kk < k0 + klen; kk += BKq) {
#pragma unroll
        for (int i = 0; i < 2; i++) {
            int idx = t + i * 256;
            int row = idx >> 2;
            int c4 = idx & 3;
            float4 v = *(const float4*)(A + (size_t)row * K + kk + c4 * 4);
            As[c4 * 4 + 0][row] = v.x;
            As[c4 * 4 + 1][row] = v.y;
            As[c4 * 4 + 2][row] = v.z;
            As[c4 * 4 + 3][row] = v.w;
        }
#pragma unroll
        for (int i = 0; i < 2; i++) {
            int idx = t + i * 256;
            int row = idx >> 2;
            int c4 = idx & 3;
            float4 v = *(const float4*)(W + (size_t)(nblk + row) * K + kk + c4 * 4);
            Ws[c4 * 4 + 0][row] = v.x;
            Ws[c4 * 4 + 1][row] = v.y;
            Ws[c4 * 4 + 2][row] = v.z;
            Ws[c4 * 4 + 3][row] = v.w;
        }
        __syncthreads();
#pragma unroll
        for (int k = 0; k < BKq; ++k) {
            float4 a0 = *(const float4*)&As[k][tm];
            float4 a1 = *(const float4*)&As[k][tm + 4];
            float4 b0 = *(const float4*)&Ws[k][tn];
            float4 b1 = *(const float4*)&Ws[k][tn + 4];
            float av[8] = {a0.x, a0.y, a0.z, a0.w, a1.x, a1.y, a1.z, a1.w};
            float bv[8] = {b0.x, b0.y, b0.z, b0.w, b1.x, b1.y, b1.z, b1.w};
#pragma unroll
            for (int i = 0; i < 8; i++)
#pragma unroll
                for (int j = 0; j < 8; j++)
                    acc[i][j] += av[i] * bv[j];
        }
        __syncthreads();
    }

    if (ksplit > 1) {
        float* P = Cpart + (size_t)blockIdx.y * 128 * N;
#pragma unroll
        for (int i = 0; i < 8; i++) {
            float* row = P + (size_t)(tm + i) * N + nblk + tn;
            *(float4*)(row)     = make_float4(acc[i][0], acc[i][1], acc[i][2], acc[i][3]);
            *(float4*)(row + 4) = make_float4(acc[i][4], acc[i][5], acc[i][6], acc[i][7]);
        }
    } else {
#pragma unroll
        for (int i = 0; i < 8; i++) {
            float* row = C + (size_t)(tm + i) * N + nblk + tn;
#pragma unroll
            for (int j = 0; j < 8; j++) {
                float c = acc[i][j] + (bias ? bias[nblk + tn + j] : 0.f);
                if (act == 1) c = tanhf(c);
                row[j] = c;
            }
        }
    }
}

__global__ void reduce_split(const float* __restrict__ part, const float* __restrict__ bias,
                             float* __restrict__ C, int total, int N, int ksplit, int act)
{
    int idx = blockIdx.x * 256 + threadIdx.x;
    if (idx >= total) return;
    float s = 0.f;
    for (int z = 0; z < ksplit; z++) s += part[(size_t)z * total + idx];
    s += bias[idx % N];
    if (act == 1) s = tanhf(s);
    C[idx] = s;
}

// ---------------- GRU gates ----------------
__global__ void gate_kernel(const float* __restrict__ hprev, float* __restrict__ out_h)
{
    int idx = blockIdx.x * 256 + threadIdx.x;   // B*H
    int b = idx >> 9;
    int j = idx & 511;
    const float* gx = g_gx + (size_t)b * 3 * Hq;
    const float* gh = g_gh + (size_t)b * 3 * Hq;
    float r = 1.f / (1.f + __expf(-(gx[j] + gh[j])));
    float z = 1.f / (1.f + __expf(-(gx[Hq + j] + gh[Hq + j])));
    float n = tanhf(gx[2 * Hq + j] + r * gh[2 * Hq + j]);
    float hn = (1.f - z) * n + z * hprev[idx];
    g_hnew[idx] = hn;
    g_concat_in[(size_t)b * 2 * Hq + j] = hn;
    if (out_h) out_h[idx] = hn;
}

// ---------------- fused attention: single pass over enc ----------------
// grid (8, B), block 256 = 8 warps. Warp w of block sblk owns chunk = sblk*8+w,
// i.e. s in [chunk*64, chunk*64+64). Warp-private online softmax with full-H ctx
// held in registers (16 floats/lane). Writes raw scores + per-chunk (m, Z, ctx).
__global__ __launch_bounds__(256)
void attn_fused_kernel(const float* __restrict__ enc)
{
    int b = blockIdx.y;
    int t = threadIdx.x;
    int w = t >> 5;
    int lane = t & 31;
    int chunk = blockIdx.x * 8 + w;

    // h fragment for this lane (matches e-load pattern)
    const float4* h4 = (const float4*)(g_hnew + (size_t)b * Hq);
    float4 h0 = h4[lane];
    float4 h1 = h4[lane + 32];
    float4 h2 = h4[lane + 64];
    float4 h3 = h4[lane + 96];

    float m = -1e30f, Z = 0.f;
    float4 c0 = make_float4(0.f,0.f,0.f,0.f), c1 = c0, c2 = c0, c3 = c0;

    int sbase = chunk * 64;
#pragma unroll 2
    for (int s0 = 0; s0 < 64; s0++) {
        int s = sbase + s0;
        const float4* e4 = (const float4*)(enc + ((size_t)s * Bq + b) * Hq);
        float4 e0 = e4[lane];
        float4 e1 = e4[lane + 32];
        float4 e2 = e4[lane + 64];
        float4 e3 = e4[lane + 96];
        float dp = e0.x*h0.x + e0.y*h0.y + e0.z*h0.z + e0.w*h0.w
                 + e1.x*h1.x + e1.y*h1.y + e1.z*h1.z + e1.w*h1.w
                 + e2.x*h2.x + e2.y*h2.y + e2.z*h2.z + e2.w*h2.w
                 + e3.x*h3.x + e3.y*h3.y + e3.z*h3.z + e3.w*h3.w;
#pragma unroll
        for (int off = 16; off > 0; off >>= 1)
            dp += __shfl_xor_sync(0xffffffffu, dp, off);
        if (lane == 0) g_scores[(size_t)b * Sq + s] = dp;
        float mn = fmaxf(m, dp);
        float corr = __expf(m - mn);      // 0 on first iter (m=-1e30)
        float p = __expf(dp - mn);
        Z = Z * corr + p;
        c0.x = c0.x*corr + p*e0.x; c0.y = c0.y*corr + p*e0.y; c0.z = c0.z*corr + p*e0.z; c0.w = c0.w*corr + p*e0.w;
        c1.x = c1.x*corr + p*e1.x; c1.y = c1.y*corr + p*e1.y; c1.z = c1.z*corr + p*e1.z; c1.w = c1.w*corr + p*e1.w;
        c2.x = c2.x*corr + p*e2.x; c2.y = c2.y*corr + p*e2.y; c2.z = c2.z*corr + p*e2.z; c2.w = c2.w*corr + p*e2.w;
        c3.x = c3.x*corr + p*e3.x; c3.y = c3.y*corr + p*e3.y; c3.z = c3.z*corr + p*e3.z; c3.w = c3.w*corr + p*e3.w;
        m = mn;
    }

    int pc = b * NCHUNK + chunk;
    float4* pctx = (float4*)(g_pctx + (size_t)pc * Hq);
    pctx[lane]      = c0;
    pctx[lane + 32] = c1;
    pctx[lane + 64] = c2;
    pctx[lane + 96] = c3;
    if (lane == 0) { g_pm[pc] = m; g_pz[pc] = Z; }
}

// ---------------- combine per-chunk partials -> context, M, 1/Z ----------------
__global__ __launch_bounds__(128)
void attn_reduce_kernel()
{
    __shared__ float scale[NCHUNK];
    __shared__ float sm[NCHUNK];
    __shared__ float sz[NCHUNK];
    __shared__ float sM, sZinv;
    int b = blockIdx.x;
    int t = threadIdx.x;
    if (t < NCHUNK) { sm[t] = g_pm[b * NCHUNK + t]; sz[t] = g_pz[b * NCHUNK + t]; }
    __syncthreads();
    if (t == 0) {
        float M = -1e30f;
        for (int c = 0; c < NCHUNK; c++) M = fmaxf(M, sm[c]);
        float Zt = 0.f;
        for (int c = 0; c < NCHUNK; c++) {
            float sc = __expf(sm[c] - M);
            scale[c] = sc;
            Zt += sz[c] * sc;
        }
        sM = M;
        sZinv = 1.f / Zt;
        g_M[b] = M;
        g_Zinv[b] = sZinv;
    }
    __syncthreads();
    float zinv = sZinv;
    // each thread handles 4 consecutive H components
    float a0 = 0.f, a1 = 0.f, a2 = 0.f, a3 = 0.f;
    for (int c = 0; c < NCHUNK; c++) {
        const float4 v = *(const float4*)(g_pctx + ((size_t)(b * NCHUNK + c)) * Hq + t * 4);
        float sc = scale[c];
        a0 += v.x * sc; a1 += v.y * sc; a2 += v.z * sc; a3 += v.w * sc;
    }
    float4 r = make_float4(a0 * zinv, a1 * zinv, a2 * zinv, a3 * zinv);
    *(float4*)(g_concat_in + (size_t)b * 2 * Hq + Hq + t * 4) = r;
}

// ---------------- attn weights output from raw scores ----------------
__global__ void attn_weights_kernel(float* __restrict__ out_attn)
{
    int idx = blockIdx.x * 256 + threadIdx.x;   // B*S
    int b = idx >> 12;                           // /S
    float v = __expf(g_scores[idx] - g_M[b]) * g_Zinv[b];
    out_attn[idx] = v;
}

// ---------------- launch ----------------
extern "C" void kernel_launch(void* const* d_in, const int* in_sizes, int n_in,
                              void* d_out, int out_size)
{
    const int* input_seq   = (const int*)d_in[0];
    const int* positions   = (const int*)d_in[1];
    const int* years       = (const int*)d_in[2];
    const int* froms       = (const int*)d_in[3];
    const float* last_h    = (const float*)d_in[4];
    const float* enc       = (const float*)d_in[5];
    const float* emb_tok   = (const float*)d_in[6];
    const float* emb_pos   = (const float*)d_in[7];
    const float* emb_year  = (const float*)d_in[8];
    const float* emb_inst  = (const float*)d_in[9];
    const float* W_ih      = (const float*)d_in[10];
    const float* b_ih      = (const float*)d_in[11];
    const float* W_hh      = (const float*)d_in[12];
    const float* b_hh      = (const float*)d_in[13];
    const float* W_concat  = (const float*)d_in[14];
    const float* b_concat  = (const float*)d_in[15];
    const float* W_out     = (const float*)d_in[16];
    const float* b_out     = (const float*)d_in[17];

    float* out = (float*)d_out;
    float* out_logits = out;
    float* out_h = nullptr;
    float* out_attn = nullptr;
    long long need = (long long)Bq * Vq + (long long)Bq * Hq + (long long)Bq * Sq;
    if ((long long)out_size >= need) {
        out_h = out + (size_t)Bq * Vq;
        out_attn = out_h + (size_t)Bq * Hq;
    }

    float *gx, *gh, *xbuf, *part, *concat_in, *concat_out;
    cudaGetSymbolAddress((void**)&gx, g_gx);
    cudaGetSymbolAddress((void**)&gh, g_gh);
    cudaGetSymbolAddress((void**)&xbuf, g_x);
    cudaGetSymbolAddress((void**)&part, g_gemm_part);
    cudaGetSymbolAddress((void**)&concat_in, g_concat_in);
    cudaGetSymbolAddress((void**)&concat_out, g_concat_out);

    // 1. embeddings -> x [B,4H]
    embed_kernel<<<256, 256>>>(input_seq, positions, years, froms,
                               emb_tok, emb_pos, emb_year, emb_inst);
    // 2. gx = x @ W_ih^T + b_ih   (split-K 8)
    gemm128<<<dim3(12, 8), 256>>>(xbuf, 4 * Hq, W_ih, nullptr, nullptr, 3 * Hq, part, 0);
    reduce_split<<<(Bq * 3 * Hq + 255) / 256, 256>>>(part, b_ih, gx, Bq * 3 * Hq, 3 * Hq, 8, 0);
    // 3. gh = h @ W_hh^T + b_hh   (split-K 8)
    gemm128<<<dim3(12, 8), 256>>>(last_h, Hq, W_hh, nullptr, nullptr, 3 * Hq, part, 0);
    reduce_split<<<(Bq * 3 * Hq + 255) / 256, 256>>>(part, b_hh, gh, Bq * 3 * Hq, 3 * Hq, 8, 0);
    // 4. gates -> h_new
    gate_kernel<<<(Bq * Hq) / 256, 256>>>(last_h, out_h);
    // 5. fused scores + online-softmax context (single pass over enc)
    attn_fused_kernel<<<dim3(8, Bq), 256>>>(enc);
    // 6. combine chunk partials -> context + (M, 1/Z)
    attn_reduce_kernel<<<Bq, 128>>>();
    // 7. attention weights output
    if (out_attn)
        attn_weights_kernel<<<(Bq * Sq) / 256, 256>>>(out_attn);
    // 8. concat_out = tanh(concat_in @ W_concat^T + b_concat) (split-K 8)
    gemm128<<<dim3(4, 8), 256>>>(concat_in, 2 * Hq, W_concat, nullptr, nullptr, Hq, part, 0);
    reduce_split<<<(Bq * Hq + 255) / 256, 256>>>(part, b_concat, concat_out, Bq * Hq, Hq, 8, 1);
    // 9. logits = concat_out @ W_out^T + b_out  (split-K 4 for occupancy/balance)
    gemm128<<<dim3(Vq / 128, 4), 256>>>(concat_out, Hq, W_out, nullptr, nullptr, Vq, part, 0);
    reduce_split<<<(Bq * Vq + 255) / 256, 256>>>(part, b_out, out_logits, Bq * Vq, Vq, 4, 0);
}

// round 4
// speedup vs baseline: 1.3539x; 1.0715x over previous
#include <cuda_runtime.h>
#include <cuda_bf16.h>
#include <math.h>
#include <stdint.h>

#define Bq 128
#define Sq 4096
#define Hq 512
#define Vq 32000
#define NCHUNK 64

// ---------------- scratch (no allocations allowed) ----------------
__device__ float g_x[Bq * 4 * Hq];
__device__ float g_gx[Bq * 3 * Hq];
__device__ float g_gh[Bq * 3 * Hq];
__device__ float g_hnew[Bq * Hq];
__device__ float g_scores[Bq * Sq];
__device__ float g_pm[Bq * NCHUNK];
__device__ float g_pz[Bq * NCHUNK];
__device__ float g_pctx[Bq * NCHUNK * Hq];
__device__ float g_M[Bq];
__device__ float g_Zinv[Bq];
__device__ float g_concat_in[Bq * 2 * Hq];
__device__ float g_concat_out[Bq * Hq];
__device__ float g_gemm_part[8 * Bq * 3 * Hq];   // split-K partials (max: gx)

// ---------------- embedding gather ----------------
__global__ void embed_kernel(const int* __restrict__ seq, const int* __restrict__ pos,
                             const int* __restrict__ yr, const int* __restrict__ fr,
                             const float* __restrict__ et, const float* __restrict__ ep,
                             const float* __restrict__ ey, const float* __restrict__ ei)
{
    int idx = blockIdx.x * 256 + threadIdx.x;
    int b = idx >> 9;
    int c = idx & 511;
    int region = c >> 7;
    int off = c & 127;
    const float* tbl; int r;
    if (region == 0)      { tbl = et; r = seq[b]; }
    else if (region == 1) { tbl = ep; r = pos[b]; }
    else if (region == 2) { tbl = ey; r = yr[b]; }
    else                  { tbl = ei; r = fr[b]; }
    float4 v = ((const float4*)(tbl + (size_t)r * Hq))[off];
    ((float4*)g_x)[idx] = v;
}

// ---------------- tf32x3 tensor-core GEMM ----------------
// C[128, N] = A[128, K] @ W[N, K]^T  via m16n8k8 tf32 mma, hi/lo split (3 mma).
// grid (N/128, ksplit). ksplit>1 -> partials to Cpart; else bias + direct C.
__device__ __forceinline__ uint32_t f2tf32(float x) {
    uint32_t r;
    asm("cvt.rna.tf32.f32 %0, %1;" : "=r"(r) : "f"(x));
    return r;
}
__device__ __forceinline__ void mma_tf32(float* d, const uint32_t* a, const uint32_t* b) {
    asm("mma.sync.aligned.m16n8k8.row.col.f32.tf32.tf32.f32 "
        "{%0,%1,%2,%3}, {%4,%5,%6,%7}, {%8,%9}, {%0,%1,%2,%3};"
        : "+f"(d[0]), "+f"(d[1]), "+f"(d[2]), "+f"(d[3])
        : "r"(a[0]), "r"(a[1]), "r"(a[2]), "r"(a[3]), "r"(b[0]), "r"(b[1]));
}

#define LDA 20   // padded stride for [row][16] tiles; (20r+k)%32 conflict-free

__global__ __launch_bounds__(256, 2)
void gemm_tf32(const float* __restrict__ A, int K,
               const float* __restrict__ W,
               const float* __restrict__ bias,
               float* __restrict__ C, int N,
               float* __restrict__ Cpart)
{
    __shared__ float Ah[128 * LDA], Al[128 * LDA];
    __shared__ float Wh[128 * LDA], Wl[128 * LDA];

    int t = threadIdx.x;
    int wid = t >> 5, lane = t & 31;
    int lr = lane >> 2, lc = lane & 3;
    int m0 = (wid & 3) * 32;
    int n0 = (wid >> 2) * 64;
    int nblk = blockIdx.x * 128;
    int ksplit = gridDim.y;
    int klen = K / ksplit;
    int kstart = blockIdx.y * klen;

    float acc[2][8][4];
#pragma unroll
    for (int i = 0; i < 2; i++)
#pragma unroll
        for (int j = 0; j < 8; j++)
#pragma unroll
            for (int c = 0; c < 4; c++) acc[i][j][c] = 0.f;

    for (int kk = kstart; kk < kstart + klen; kk += 16) {
        // stage A and W tiles (128 x 16), split into tf32 hi/lo
#pragma unroll
        for (int i = 0; i < 2; i++) {
            int idx = t + i * 256;          // 0..511
            int r = idx >> 2;
            int k4 = (idx & 3) * 4;
            float4 va = *(const float4*)(A + (size_t)r * K + kk + k4);
            float4 vw = *(const float4*)(W + (size_t)(nblk + r) * K + kk + k4);
            float av[4] = {va.x, va.y, va.z, va.w};
            float wv[4] = {vw.x, vw.y, vw.z, vw.w};
#pragma unroll
            for (int d = 0; d < 4; d++) {
                uint32_t hi = f2tf32(av[d]);
                float hif = __uint_as_float(hi);
                Ah[r * LDA + k4 + d] = hif;
                Al[r * LDA + k4 + d] = __uint_as_float(f2tf32(av[d] - hif));
                uint32_t whi = f2tf32(wv[d]);
                float whif = __uint_as_float(whi);
                Wh[r * LDA + k4 + d] = whif;
                Wl[r * LDA + k4 + d] = __uint_as_float(f2tf32(wv[d] - whif));
            }
        }
        __syncthreads();

#pragma unroll
        for (int ks = 0; ks < 2; ks++) {
            int k0 = ks * 8;
            uint32_t ah[2][4], al[2][4];
#pragma unroll
            for (int tt = 0; tt < 2; tt++) {
                int rb = m0 + tt * 16;
                ah[tt][0] = __float_as_uint(Ah[(rb + lr) * LDA + k0 + lc]);
                ah[tt][1] = __float_as_uint(Ah[(rb + lr + 8) * LDA + k0 + lc]);
                ah[tt][2] = __float_as_uint(Ah[(rb + lr) * LDA + k0 + lc + 4]);
                ah[tt][3] = __float_as_uint(Ah[(rb + lr + 8) * LDA + k0 + lc + 4]);
                al[tt][0] = __float_as_uint(Al[(rb + lr) * LDA + k0 + lc]);
                al[tt][1] = __float_as_uint(Al[(rb + lr + 8) * LDA + k0 + lc]);
                al[tt][2] = __float_as_uint(Al[(rb + lr) * LDA + k0 + lc + 4]);
                al[tt][3] = __float_as_uint(Al[(rb + lr + 8) * LDA + k0 + lc + 4]);
            }
#pragma unroll
            for (int j = 0; j < 8; j++) {
                int rn = (n0 + j * 8 + lr) * LDA;
                uint32_t bh[2], bl[2];
                bh[0] = __float_as_uint(Wh[rn + k0 + lc]);
                bh[1] = __float_as_uint(Wh[rn + k0 + lc + 4]);
                bl[0] = __float_as_uint(Wl[rn + k0 + lc]);
                bl[1] = __float_as_uint(Wl[rn + k0 + lc + 4]);
#pragma unroll
                for (int tt = 0; tt < 2; tt++) {
                    mma_tf32(acc[tt][j], ah[tt], bh);
                    mma_tf32(acc[tt][j], ah[tt], bl);
                    mma_tf32(acc[tt][j], al[tt], bh);
                }
            }
        }
        __syncthreads();
    }

    // epilogue
    if (ksplit > 1) {
        float* P = Cpart + (size_t)blockIdx.y * 128 * N;
#pragma unroll
        for (int tt = 0; tt < 2; tt++)
#pragma unroll
            for (int j = 0; j < 8; j++) {
                int gr = m0 + tt * 16 + lr;
                int gc = nblk + n0 + j * 8 + 2 * lc;
                *(float2*)(P + (size_t)gr * N + gc) = make_float2(acc[tt][j][0], acc[tt][j][1]);
                *(float2*)(P + (size_t)(gr + 8) * N + gc) = make_float2(acc[tt][j][2], acc[tt][j][3]);
            }
    } else {
#pragma unroll
        for (int tt = 0; tt < 2; tt++)
#pragma unroll
            for (int j = 0; j < 8; j++) {
                int gr = m0 + tt * 16 + lr;
                int gc = nblk + n0 + j * 8 + 2 * lc;
                float b0 = bias ? bias[gc] : 0.f;
                float b1 = bias ? bias[gc + 1] : 0.f;
                *(float2*)(C + (size_t)gr * N + gc) = make_float2(acc[tt][j][0] + b0, acc[tt][j][1] + b1);
                *(float2*)(C + (size_t)(gr + 8) * N + gc) = make_float2(acc[tt][j][2] + b0, acc[tt][j][3] + b1);
            }
    }
}

__global__ void reduce_split(const float* __restrict__ part, const float* __restrict__ bias,
                             float* __restrict__ C, int total, int N, int ksplit, int act)
{
    int idx = blockIdx.x * 256 + threadIdx.x;
    if (idx >= total) return;
    float s = 0.f;
    for (int z = 0; z < ksplit; z++) s += part[(size_t)z * total + idx];
    s += bias[idx % N];
    if (act == 1) s = tanhf(s);
    C[idx] = s;
}

// ---------------- GRU gates ----------------
__global__ void gate_kernel(const float* __restrict__ hprev, float* __restrict__ out_h)
{
    int idx = blockIdx.x * 256 + threadIdx.x;
    int b = idx >> 9;
    int j = idx & 511;
    const float* gx = g_gx + (size_t)b * 3 * Hq;
    const float* gh = g_gh + (size_t)b * 3 * Hq;
    float r = 1.f / (1.f + __expf(-(gx[j] + gh[j])));
    float z = 1.f / (1.f + __expf(-(gx[Hq + j] + gh[Hq + j])));
    float n = tanhf(gx[2 * Hq + j] + r * gh[2 * Hq + j]);
    float hn = (1.f - z) * n + z * hprev[idx];
    g_hnew[idx] = hn;
    g_concat_in[(size_t)b * 2 * Hq + j] = hn;
    if (out_h) out_h[idx] = hn;
}

// ---------------- fused attention: single pass over enc ----------------
__global__ __launch_bounds__(256)
void attn_fused_kernel(const float* __restrict__ enc)
{
    int b = blockIdx.y;
    int t = threadIdx.x;
    int w = t >> 5;
    int lane = t & 31;
    int chunk = blockIdx.x * 8 + w;

    const float4* h4 = (const float4*)(g_hnew + (size_t)b * Hq);
    float4 h0 = h4[lane];
    float4 h1 = h4[lane + 32];
    float4 h2 = h4[lane + 64];
    float4 h3 = h4[lane + 96];

    float m = -1e30f, Z = 0.f;
    float4 c0 = make_float4(0.f,0.f,0.f,0.f), c1 = c0, c2 = c0, c3 = c0;

    int sbase = chunk * 64;
#pragma unroll 2
    for (int s0 = 0; s0 < 64; s0++) {
        int s = sbase + s0;
        const float4* e4 = (const float4*)(enc + ((size_t)s * Bq + b) * Hq);
        float4 e0 = e4[lane];
        float4 e1 = e4[lane + 32];
        float4 e2 = e4[lane + 64];
        float4 e3 = e4[lane + 96];
        float dp = e0.x*h0.x + e0.y*h0.y + e0.z*h0.z + e0.w*h0.w
                 + e1.x*h1.x + e1.y*h1.y + e1.z*h1.z + e1.w*h1.w
                 + e2.x*h2.x + e2.y*h2.y + e2.z*h2.z + e2.w*h2.w
                 + e3.x*h3.x + e3.y*h3.y + e3.z*h3.z + e3.w*h3.w;
#pragma unroll
        for (int off = 16; off > 0; off >>= 1)
            dp += __shfl_xor_sync(0xffffffffu, dp, off);
        if (lane == 0) g_scores[(size_t)b * Sq + s] = dp;
        float mn = fmaxf(m, dp);
        float corr = __expf(m - mn);
        float p = __expf(dp - mn);
        Z = Z * corr + p;
        c0.x = c0.x*corr + p*e0.x; c0.y = c0.y*corr + p*e0.y; c0.z = c0.z*corr + p*e0.z; c0.w = c0.w*corr + p*e0.w;
        c1.x = c1.x*corr + p*e1.x; c1.y = c1.y*corr + p*e1.y; c1.z = c1.z*corr + p*e1.z; c1.w = c1.w*corr + p*e1.w;
        c2.x = c2.x*corr + p*e2.x; c2.y = c2.y*corr + p*e2.y; c2.z = c2.z*corr + p*e2.z; c2.w = c2.w*corr + p*e2.w;
        c3.x = c3.x*corr + p*e3.x; c3.y = c3.y*corr + p*e3.y; c3.z = c3.z*corr + p*e3.z; c3.w = c3.w*corr + p*e3.w;
        m = mn;
    }

    int pc = b * NCHUNK + chunk;
    float4* pctx = (float4*)(g_pctx + (size_t)pc * Hq);
    pctx[lane]      = c0;
    pctx[lane + 32] = c1;
    pctx[lane + 64] = c2;
    pctx[lane + 96] = c3;
    if (lane == 0) { g_pm[pc] = m; g_pz[pc] = Z; }
}

// ---------------- combine per-chunk partials -> context, M, 1/Z ----------------
__global__ __launch_bounds__(128)
void attn_reduce_kernel()
{
    __shared__ float scale[NCHUNK];
    __shared__ float sm[NCHUNK];
    __shared__ float sz[NCHUNK];
    __shared__ float sM, sZinv;
    int b = blockIdx.x;
    int t = threadIdx.x;
    if (t < NCHUNK) { sm[t] = g_pm[b * NCHUNK + t]; sz[t] = g_pz[b * NCHUNK + t]; }
    __syncthreads();
    if (t == 0) {
        float M = -1e30f;
        for (int c = 0; c < NCHUNK; c++) M = fmaxf(M, sm[c]);
        float Zt = 0.f;
        for (int c = 0; c < NCHUNK; c++) {
            float sc = __expf(sm[c] - M);
            scale[c] = sc;
            Zt += sz[c] * sc;
        }
        sM = M;
        sZinv = 1.f / Zt;
        g_M[b] = M;
        g_Zinv[b] = sZinv;
    }
    __syncthreads();
    float zinv = sZinv;
    float a0 = 0.f, a1 = 0.f, a2 = 0.f, a3 = 0.f;
    for (int c = 0; c < NCHUNK; c++) {
        const float4 v = *(const float4*)(g_pctx + ((size_t)(b * NCHUNK + c)) * Hq + t * 4);
        float sc = scale[c];
        a0 += v.x * sc; a1 += v.y * sc; a2 += v.z * sc; a3 += v.w * sc;
    }
    float4 r = make_float4(a0 * zinv, a1 * zinv, a2 * zinv, a3 * zinv);
    *(float4*)(g_concat_in + (size_t)b * 2 * Hq + Hq + t * 4) = r;
}

// ---------------- attn weights output from raw scores ----------------
__global__ void attn_weights_kernel(float* __restrict__ out_attn)
{
    int idx = blockIdx.x * 256 + threadIdx.x;
    int b = idx >> 12;
    float v = __expf(g_scores[idx] - g_M[b]) * g_Zinv[b];
    out_attn[idx] = v;
}

// ---------------- launch ----------------
extern "C" void kernel_launch(void* const* d_in, const int* in_sizes, int n_in,
                              void* d_out, int out_size)
{
    const int* input_seq   = (const int*)d_in[0];
    const int* positions   = (const int*)d_in[1];
    const int* years       = (const int*)d_in[2];
    const int* froms       = (const int*)d_in[3];
    const float* last_h    = (const float*)d_in[4];
    const float* enc       = (const float*)d_in[5];
    const float* emb_tok   = (const float*)d_in[6];
    const float* emb_pos   = (const float*)d_in[7];
    const float* emb_year  = (const float*)d_in[8];
    const float* emb_inst  = (const float*)d_in[9];
    const float* W_ih      = (const float*)d_in[10];
    const float* b_ih      = (const float*)d_in[11];
    const float* W_hh      = (const float*)d_in[12];
    const float* b_hh      = (const float*)d_in[13];
    const float* W_concat  = (const float*)d_in[14];
    const float* b_concat  = (const float*)d_in[15];
    const float* W_out     = (const float*)d_in[16];
    const float* b_out     = (const float*)d_in[17];

    float* out = (float*)d_out;
    float* out_logits = out;
    float* out_h = nullptr;
    float* out_attn = nullptr;
    long long need = (long long)Bq * Vq + (long long)Bq * Hq + (long long)Bq * Sq;
    if ((long long)out_size >= need) {
        out_h = out + (size_t)Bq * Vq;
        out_attn = out_h + (size_t)Bq * Hq;
    }

    float *gx, *gh, *xbuf, *part, *concat_in, *concat_out;
    cudaGetSymbolAddress((void**)&gx, g_gx);
    cudaGetSymbolAddress((void**)&gh, g_gh);
    cudaGetSymbolAddress((void**)&xbuf, g_x);
    cudaGetSymbolAddress((void**)&part, g_gemm_part);
    cudaGetSymbolAddress((void**)&concat_in, g_concat_in);
    cudaGetSymbolAddress((void**)&concat_out, g_concat_out);

    // 1. embeddings -> x [B,4H]
    embed_kernel<<<256, 256>>>(input_seq, positions, years, froms,
                               emb_tok, emb_pos, emb_year, emb_inst);
    // 2. gx = x @ W_ih^T + b_ih   (tf32x3, split-K 8)
    gemm_tf32<<<dim3(12, 8), 256>>>(xbuf, 4 * Hq, W_ih, nullptr, nullptr, 3 * Hq, part);
    reduce_split<<<(Bq * 3 * Hq + 255) / 256, 256>>>(part, b_ih, gx, Bq * 3 * Hq, 3 * Hq, 8, 0);
    // 3. gh = h @ W_hh^T + b_hh   (tf32x3, split-K 4)
    gemm_tf32<<<dim3(12, 4), 256>>>(last_h, Hq, W_hh, nullptr, nullptr, 3 * Hq, part);
    reduce_split<<<(Bq * 3 * Hq + 255) / 256, 256>>>(part, b_hh, gh, Bq * 3 * Hq, 3 * Hq, 4, 0);
    // 4. gates -> h_new
    gate_kernel<<<(Bq * Hq) / 256, 256>>>(last_h, out_h);
    // 5. fused scores + online-softmax context (single pass over enc)
    attn_fused_kernel<<<dim3(8, Bq), 256>>>(enc);
    // 6. combine chunk partials -> context + (M, 1/Z)
    attn_reduce_kernel<<<Bq, 128>>>();
    // 7. attention weights output
    if (out_attn)
        attn_weights_kernel<<<(Bq * Sq) / 256, 256>>>(out_attn);
    // 8. concat_out = tanh(concat_in @ W_concat^T + b_concat) (tf32x3, split-K 8)
    gemm_tf32<<<dim3(4, 8), 256>>>(concat_in, 2 * Hq, W_concat, nullptr, nullptr, Hq, part);
    reduce_split<<<(Bq * Hq + 255) / 256, 256>>>(part, b_concat, concat_out, Bq * Hq, Hq, 8, 1);
    // 9. logits = concat_out @ W_out^T + b_out  (tf32x3, split-K 1, bias fused, direct out)
    gemm_tf32<<<dim3(Vq / 128, 1), 256>>>(concat_out, Hq, W_out, b_out, out_logits, Vq, nullptr);
}

// round 5
// speedup vs baseline: 1.4189x; 1.0481x over previous
#include <cuda_runtime.h>
#include <cuda_bf16.h>
#include <math.h>
#include <stdint.h>

#define Bq 128
#define Sq 4096
#define Hq 512
#define Vq 32000
#define NCHUNK 64

// ---------------- scratch (no allocations allowed) ----------------
__device__ float g_x[Bq * 4 * Hq];
__device__ float g_hnew[Bq * Hq];
__device__ float g_scores[Bq * Sq];
__device__ float g_pm[Bq * NCHUNK];
__device__ float g_pz[Bq * NCHUNK];
__device__ float g_pctx[Bq * NCHUNK * Hq];
__device__ float g_M[Bq];
__device__ float g_Zinv[Bq];
__device__ float g_concat_in[Bq * 2 * Hq];
__device__ float g_concat_out[Bq * Hq];
__device__ float g_gemm_part [8 * Bq * 3 * Hq];  // gx partials (and general split-K scratch)
__device__ float g_gemm_part2[8 * Bq * 3 * Hq];  // gh partials

// ---------------- embedding gather ----------------
__global__ void embed_kernel(const int* __restrict__ seq, const int* __restrict__ pos,
                             const int* __restrict__ yr, const int* __restrict__ fr,
                             const float* __restrict__ et, const float* __restrict__ ep,
                             const float* __restrict__ ey, const float* __restrict__ ei)
{
    int idx = blockIdx.x * 256 + threadIdx.x;
    int b = idx >> 9;
    int c = idx & 511;
    int region = c >> 7;
    int off = c & 127;
    const float* tbl; int r;
    if (region == 0)      { tbl = et; r = seq[b]; }
    else if (region == 1) { tbl = ep; r = pos[b]; }
    else if (region == 2) { tbl = ey; r = yr[b]; }
    else                  { tbl = ei; r = fr[b]; }
    float4 v = ((const float4*)(tbl + (size_t)r * Hq))[off];
    ((float4*)g_x)[idx] = v;
}

// ---------------- tf32x3 tensor-core GEMM body ----------------
__device__ __forceinline__ uint32_t f2tf32(float x) {
    uint32_t r;
    asm("cvt.rna.tf32.f32 %0, %1;" : "=r"(r) : "f"(x));
    return r;
}
__device__ __forceinline__ void mma_tf32(float* d, const uint32_t* a, const uint32_t* b) {
    asm("mma.sync.aligned.m16n8k8.row.col.f32.tf32.tf32.f32 "
        "{%0,%1,%2,%3}, {%4,%5,%6,%7}, {%8,%9}, {%0,%1,%2,%3};"
        : "+f"(d[0]), "+f"(d[1]), "+f"(d[2]), "+f"(d[3])
        : "r"(a[0]), "r"(a[1]), "r"(a[2]), "r"(a[3]), "r"(b[0]), "r"(b[1]));
}

#define LDA 20   // padded stride; (20r+k)%32 conflict-free

// C[128,N] = A[128,K] @ W[N,K]^T over k in [kstart, kstart+klen).
// part!=null -> write raw tile to part (slab for this k-split); else bias + C.
__device__ __forceinline__
void gemm_body(const float* __restrict__ A, int K,
               const float* __restrict__ W,
               const float* __restrict__ bias,
               float* __restrict__ C, int N,
               float* __restrict__ part,
               int nblk, int kstart, int klen)
{
    __shared__ float Ah[128 * LDA], Al[128 * LDA];
    __shared__ float Wh[128 * LDA], Wl[128 * LDA];

    int t = threadIdx.x;
    int wid = t >> 5, lane = t & 31;
    int lr = lane >> 2, lc = lane & 3;
    int m0 = (wid & 3) * 32;
    int n0 = (wid >> 2) * 64;

    float acc[2][8][4];
#pragma unroll
    for (int i = 0; i < 2; i++)
#pragma unroll
        for (int j = 0; j < 8; j++)
#pragma unroll
            for (int c = 0; c < 4; c++) acc[i][j][c] = 0.f;

    for (int kk = kstart; kk < kstart + klen; kk += 16) {
#pragma unroll
        for (int i = 0; i < 2; i++) {
            int idx = t + i * 256;
            int r = idx >> 2;
            int k4 = (idx & 3) * 4;
            float4 va = *(const float4*)(A + (size_t)r * K + kk + k4);
            float4 vw = *(const float4*)(W + (size_t)(nblk + r) * K + kk + k4);
            float av[4] = {va.x, va.y, va.z, va.w};
            float wv[4] = {vw.x, vw.y, vw.z, vw.w};
#pragma unroll
            for (int d = 0; d < 4; d++) {
                uint32_t hi = f2tf32(av[d]);
                float hif = __uint_as_float(hi);
                Ah[r * LDA + k4 + d] = hif;
                Al[r * LDA + k4 + d] = __uint_as_float(f2tf32(av[d] - hif));
                uint32_t whi = f2tf32(wv[d]);
                float whif = __uint_as_float(whi);
                Wh[r * LDA + k4 + d] = whif;
                Wl[r * LDA + k4 + d] = __uint_as_float(f2tf32(wv[d] - whif));
            }
        }
        __syncthreads();

#pragma unroll
        for (int ks = 0; ks < 2; ks++) {
            int k0 = ks * 8;
            uint32_t ah[2][4], al[2][4];
#pragma unroll
            for (int tt = 0; tt < 2; tt++) {
                int rb = m0 + tt * 16;
                ah[tt][0] = __float_as_uint(Ah[(rb + lr) * LDA + k0 + lc]);
                ah[tt][1] = __float_as_uint(Ah[(rb + lr + 8) * LDA + k0 + lc]);
                ah[tt][2] = __float_as_uint(Ah[(rb + lr) * LDA + k0 + lc + 4]);
                ah[tt][3] = __float_as_uint(Ah[(rb + lr + 8) * LDA + k0 + lc + 4]);
                al[tt][0] = __float_as_uint(Al[(rb + lr) * LDA + k0 + lc]);
                al[tt][1] = __float_as_uint(Al[(rb + lr + 8) * LDA + k0 + lc]);
                al[tt][2] = __float_as_uint(Al[(rb + lr) * LDA + k0 + lc + 4]);
                al[tt][3] = __float_as_uint(Al[(rb + lr + 8) * LDA + k0 + lc + 4]);
            }
#pragma unroll
            for (int j = 0; j < 8; j++) {
                int rn = (n0 + j * 8 + lr) * LDA;
                uint32_t bh[2], bl[2];
                bh[0] = __float_as_uint(Wh[rn + k0 + lc]);
                bh[1] = __float_as_uint(Wh[rn + k0 + lc + 4]);
                bl[0] = __float_as_uint(Wl[rn + k0 + lc]);
                bl[1] = __float_as_uint(Wl[rn + k0 + lc + 4]);
#pragma unroll
                for (int tt = 0; tt < 2; tt++) {
                    mma_tf32(acc[tt][j], ah[tt], bh);
                    mma_tf32(acc[tt][j], ah[tt], bl);
                    mma_tf32(acc[tt][j], al[tt], bh);
                }
            }
        }
        __syncthreads();
    }

    if (part) {
#pragma unroll
        for (int tt = 0; tt < 2; tt++)
#pragma unroll
            for (int j = 0; j < 8; j++) {
                int gr = m0 + tt * 16 + lr;
                int gc = nblk + n0 + j * 8 + 2 * lc;
                *(float2*)(part + (size_t)gr * N + gc) = make_float2(acc[tt][j][0], acc[tt][j][1]);
                *(float2*)(part + (size_t)(gr + 8) * N + gc) = make_float2(acc[tt][j][2], acc[tt][j][3]);
            }
    } else {
#pragma unroll
        for (int tt = 0; tt < 2; tt++)
#pragma unroll
            for (int j = 0; j < 8; j++) {
                int gr = m0 + tt * 16 + lr;
                int gc = nblk + n0 + j * 8 + 2 * lc;
                float b0 = bias ? bias[gc] : 0.f;
                float b1 = bias ? bias[gc + 1] : 0.f;
                *(float2*)(C + (size_t)gr * N + gc) = make_float2(acc[tt][j][0] + b0, acc[tt][j][1] + b1);
                *(float2*)(C + (size_t)(gr + 8) * N + gc) = make_float2(acc[tt][j][2] + b0, acc[tt][j][3] + b1);
            }
    }
}

// generic GEMM: grid (N/128, ksplit); ksplit>1 -> partial slabs in Cpart
__global__ __launch_bounds__(256, 2)
void gemm_tf32(const float* __restrict__ A, int K,
               const float* __restrict__ W,
               const float* __restrict__ bias,
               float* __restrict__ C, int N,
               float* __restrict__ Cpart)
{
    int ksplit = gridDim.y;
    int klen = K / ksplit;
    float* part = (ksplit > 1) ? (Cpart + (size_t)blockIdx.y * 128 * N) : nullptr;
    gemm_body(A, K, W, bias, C, N, part, blockIdx.x * 128, blockIdx.y * klen, klen);
}

// fused GRU GEMMs: grid (12, 8, 2); z=0 -> gx (K=4H), z=1 -> gh (K=H)
__global__ __launch_bounds__(256, 2)
void gemm_gru(const float* __restrict__ hprev,
              const float* __restrict__ W_ih, const float* __restrict__ W_hh)
{
    int N = 3 * Hq;
    if (blockIdx.z == 0) {
        int K = 4 * Hq, klen = K / 8;
        gemm_body(g_x, K, W_ih, nullptr, nullptr, N,
                  g_gemm_part + (size_t)blockIdx.y * 128 * N,
                  blockIdx.x * 128, blockIdx.y * klen, klen);
    } else {
        int K = Hq, klen = K / 8;
        gemm_body(hprev, K, W_hh, nullptr, nullptr, N,
                  g_gemm_part2 + (size_t)blockIdx.y * 128 * N,
                  blockIdx.x * 128, blockIdx.y * klen, klen);
    }
}

__global__ void reduce_split(const float* __restrict__ part, const float* __restrict__ bias,
                             float* __restrict__ C, int total, int N, int ksplit, int act)
{
    int idx = blockIdx.x * 256 + threadIdx.x;
    if (idx >= total) return;
    float s = 0.f;
    for (int z = 0; z < ksplit; z++) s += part[(size_t)z * total + idx];
    s += bias[idx % N];
    if (act == 1) s = tanhf(s);
    C[idx] = s;
}

// ---------------- fused split-K reduce + GRU gates ----------------
__global__ void gate_fused_kernel(const float* __restrict__ hprev,
                                  const float* __restrict__ b_ih,
                                  const float* __restrict__ b_hh,
                                  float* __restrict__ out_h)
{
    int idx = blockIdx.x * 256 + threadIdx.x;   // B*H
    int b = idx >> 9;
    int j = idx & 511;
    float xr = 0.f, xz = 0.f, xn = 0.f, hr = 0.f, hz = 0.f, hn = 0.f;
#pragma unroll
    for (int z = 0; z < 8; z++) {
        const float* P0 = g_gemm_part  + ((size_t)z * Bq + b) * (3 * Hq);
        const float* P1 = g_gemm_part2 + ((size_t)z * Bq + b) * (3 * Hq);
        xr += P0[j]; xz += P0[Hq + j]; xn += P0[2 * Hq + j];
        hr += P1[j]; hz += P1[Hq + j]; hn += P1[2 * Hq + j];
    }
    xr += b_ih[j]; xz += b_ih[Hq + j]; xn += b_ih[2 * Hq + j];
    hr += b_hh[j]; hz += b_hh[Hq + j]; hn += b_hh[2 * Hq + j];
    float r = 1.f / (1.f + __expf(-(xr + hr)));
    float z = 1.f / (1.f + __expf(-(xz + hz)));
    float n = tanhf(xn + r * hn);
    float hnew = (1.f - z) * n + z * hprev[idx];
    g_hnew[idx] = hnew;
    g_concat_in[(size_t)b * 2 * Hq + j] = hnew;
    if (out_h) out_h[idx] = hnew;
}

// ---------------- fused attention: single pass over enc ----------------
// warp-uniform dp -> divergence-free rare-rescale online softmax
__global__ __launch_bounds__(256)
void attn_fused_kernel(const float* __restrict__ enc)
{
    int b = blockIdx.y;
    int t = threadIdx.x;
    int w = t >> 5;
    int lane = t & 31;
    int chunk = blockIdx.x * 8 + w;

    const float4* h4 = (const float4*)(g_hnew + (size_t)b * Hq);
    float4 h0 = h4[lane];
    float4 h1 = h4[lane + 32];
    float4 h2 = h4[lane + 64];
    float4 h3 = h4[lane + 96];

    float m = -1e30f, Z = 0.f;
    float4 c0 = make_float4(0.f,0.f,0.f,0.f), c1 = c0, c2 = c0, c3 = c0;

    int sbase = chunk * 64;
#pragma unroll 2
    for (int s0 = 0; s0 < 64; s0++) {
        int s = sbase + s0;
        const float4* e4 = (const float4*)(enc + ((size_t)s * Bq + b) * Hq);
        float4 e0 = e4[lane];
        float4 e1 = e4[lane + 32];
        float4 e2 = e4[lane + 64];
        float4 e3 = e4[lane + 96];
        float dp = e0.x*h0.x + e0.y*h0.y + e0.z*h0.z + e0.w*h0.w
                 + e1.x*h1.x + e1.y*h1.y + e1.z*h1.z + e1.w*h1.w
                 + e2.x*h2.x + e2.y*h2.y + e2.z*h2.z + e2.w*h2.w
                 + e3.x*h3.x + e3.y*h3.y + e3.z*h3.z + e3.w*h3.w;
#pragma unroll
        for (int off = 16; off > 0; off >>= 1)
            dp += __shfl_xor_sync(0xffffffffu, dp, off);
        if (lane == 0) g_scores[(size_t)b * Sq + s] = dp;
        if (dp <= m) {                       // warp-uniform: no divergence
            float p = __expf(dp - m);
            Z += p;
            c0.x += p*e0.x; c0.y += p*e0.y; c0.z += p*e0.z; c0.w += p*e0.w;
            c1.x += p*e1.x; c1.y += p*e1.y; c1.z += p*e1.z; c1.w += p*e1.w;
            c2.x += p*e2.x; c2.y += p*e2.y; c2.z += p*e2.z; c2.w += p*e2.w;
            c3.x += p*e3.x; c3.y += p*e3.y; c3.z += p*e3.z; c3.w += p*e3.w;
        } else {                             // rare: new max
            float corr = __expf(m - dp);
            Z = Z * corr + 1.f;
            c0.x = c0.x*corr + e0.x; c0.y = c0.y*corr + e0.y; c0.z = c0.z*corr + e0.z; c0.w = c0.w*corr + e0.w;
            c1.x = c1.x*corr + e1.x; c1.y = c1.y*corr + e1.y; c1.z = c1.z*corr + e1.z; c1.w = c1.w*corr + e1.w;
            c2.x = c2.x*corr + e2.x; c2.y = c2.y*corr + e2.y; c2.z = c2.z*corr + e2.z; c2.w = c2.w*corr + e2.w;
            c3.x = c3.x*corr + e3.x; c3.y = c3.y*corr + e3.y; c3.z = c3.z*corr + e3.z; c3.w = c3.w*corr + e3.w;
            m = dp;
        }
    }

    int pc = b * NCHUNK + chunk;
    float4* pctx = (float4*)(g_pctx + (size_t)pc * Hq);
    pctx[lane]      = c0;
    pctx[lane + 32] = c1;
    pctx[lane + 64] = c2;
    pctx[lane + 96] = c3;
    if (lane == 0) { g_pm[pc] = m; g_pz[pc] = Z; }
}

// ---------------- combine per-chunk partials -> context, M, 1/Z ----------------
__global__ __launch_bounds__(128)
void attn_reduce_kernel()
{
    __shared__ float scale[NCHUNK];
    __shared__ float sm[NCHUNK];
    __shared__ float sz[NCHUNK];
    __shared__ float sM, sZinv;
    int b = blockIdx.x;
    int t = threadIdx.x;
    if (t < NCHUNK) { sm[t] = g_pm[b * NCHUNK + t]; sz[t] = g_pz[b * NCHUNK + t]; }
    __syncthreads();
    if (t == 0) {
        float M = -1e30f;
        for (int c = 0; c < NCHUNK; c++) M = fmaxf(M, sm[c]);
        float Zt = 0.f;
        for (int c = 0; c < NCHUNK; c++) {
            float sc = __expf(sm[c] - M);
            scale[c] = sc;
            Zt += sz[c] * sc;
        }
        sM = M;
        sZinv = 1.f / Zt;
        g_M[b] = M;
        g_Zinv[b] = sZinv;
    }
    __syncthreads();
    float zinv = sZinv;
    float a0 = 0.f, a1 = 0.f, a2 = 0.f, a3 = 0.f;
    for (int c = 0; c < NCHUNK; c++) {
        const float4 v = *(const float4*)(g_pctx + ((size_t)(b * NCHUNK + c)) * Hq + t * 4);
        float sc = scale[c];
        a0 += v.x * sc; a1 += v.y * sc; a2 += v.z * sc; a3 += v.w * sc;
    }
    float4 r = make_float4(a0 * zinv, a1 * zinv, a2 * zinv, a3 * zinv);
    *(float4*)(g_concat_in + (size_t)b * 2 * Hq + Hq + t * 4) = r;
}

// ---------------- attn weights output ----------------
__global__ void attn_weights_kernel(float* __restrict__ out_attn)
{
    int idx = blockIdx.x * 256 + threadIdx.x;
    int b = idx >> 12;
    float v = __expf(g_scores[idx] - g_M[b]) * g_Zinv[b];
    out_attn[idx] = v;
}

// ---------------- launch ----------------
extern "C" void kernel_launch(void* const* d_in, const int* in_sizes, int n_in,
                              void* d_out, int out_size)
{
    const int* input_seq   = (const int*)d_in[0];
    const int* positions   = (const int*)d_in[1];
    const int* years       = (const int*)d_in[2];
    const int* froms       = (const int*)d_in[3];
    const float* last_h    = (const float*)d_in[4];
    const float* enc       = (const float*)d_in[5];
    const float* emb_tok   = (const float*)d_in[6];
    const float* emb_pos   = (const float*)d_in[7];
    const float* emb_year  = (const float*)d_in[8];
    const float* emb_inst  = (const float*)d_in[9];
    const float* W_ih      = (const float*)d_in[10];
    const float* b_ih      = (const float*)d_in[11];
    const float* W_hh      = (const float*)d_in[12];
    const float* b_hh      = (const float*)d_in[13];
    const float* W_concat  = (const float*)d_in[14];
    const float* b_concat  = (const float*)d_in[15];
    const float* W_out     = (const float*)d_in[16];
    const float* b_out     = (const float*)d_in[17];

    float* out = (float*)d_out;
    float* out_logits = out;
    float* out_h = nullptr;
    float* out_attn = nullptr;
    long long need = (long long)Bq * Vq + (long long)Bq * Hq + (long long)Bq * Sq;
    if ((long long)out_size >= need) {
        out_h = out + (size_t)Bq * Vq;
        out_attn = out_h + (size_t)Bq * Hq;
    }

    float *part, *concat_in, *concat_out;
    cudaGetSymbolAddress((void**)&part, g_gemm_part);
    cudaGetSymbolAddress((void**)&concat_in, g_concat_in);
    cudaGetSymbolAddress((void**)&concat_out, g_concat_out);

    // 1. embeddings -> x [B,4H]
    embed_kernel<<<256, 256>>>(input_seq, positions, years, froms,
                               emb_tok, emb_pos, emb_year, emb_inst);
    // 2. gx AND gh in one launch (split-K 8 each, partials)
    gemm_gru<<<dim3(12, 8, 2), 256>>>(last_h, W_ih, W_hh);
    // 3. fused split-K reduce + gates -> h_new
    gate_fused_kernel<<<(Bq * Hq) / 256, 256>>>(last_h, b_ih, b_hh, out_h);
    // 4. fused scores + online-softmax context (single pass over enc)
    attn_fused_kernel<<<dim3(8, Bq), 256>>>(enc);
    // 5. combine chunk partials -> context + (M, 1/Z)
    attn_reduce_kernel<<<Bq, 128>>>();
    // 6. attention weights output
    if (out_attn)
        attn_weights_kernel<<<(Bq * Sq) / 256, 256>>>(out_attn);
    // 7. concat_out = tanh(concat_in @ W_concat^T + b_concat) (split-K 8)
    gemm_tf32<<<dim3(4, 8), 256>>>(concat_in, 2 * Hq, W_concat, nullptr, nullptr, Hq, part);
    reduce_split<<<(Bq * Hq + 255) / 256, 256>>>(part, b_concat, concat_out, Bq * Hq, Hq, 8, 1);
    // 8. logits = concat_out @ W_out^T + b_out  (split-K 1, bias fused, direct out)
    gemm_tf32<<<dim3(Vq / 128, 1), 256>>>(concat_out, Hq, W_out, b_out, out_logits, Vq, nullptr);
}

// round 6
// speedup vs baseline: 1.6271x; 1.1467x over previous
#include <cuda_runtime.h>
#include <cuda_bf16.h>
#include <math.h>
#include <stdint.h>

#define Bq 128
#define Sq 4096
#define Hq 512
#define Vq 32000
#define NCHUNK 64

// ---------------- scratch (no allocations allowed) ----------------
__device__ float g_x[Bq * 4 * Hq];
__device__ float g_hnew[Bq * Hq];
__device__ float g_scores[Bq * Sq];
__device__ float g_pm[Bq * NCHUNK];
__device__ float g_pz[Bq * NCHUNK];
__device__ float g_pctx[Bq * NCHUNK * Hq];
__device__ float g_concat_in[Bq * 2 * Hq];
__device__ float g_concat_out[Bq * Hq];
__device__ float g_gemm_part [8 * Bq * 3 * Hq];  // gx partials / general split-K scratch
__device__ float g_gemm_part2[8 * Bq * 3 * Hq];  // gh partials

// ---------------- embedding gather ----------------
__global__ void embed_kernel(const int* __restrict__ seq, const int* __restrict__ pos,
                             const int* __restrict__ yr, const int* __restrict__ fr,
                             const float* __restrict__ et, const float* __restrict__ ep,
                             const float* __restrict__ ey, const float* __restrict__ ei)
{
    int idx = blockIdx.x * 256 + threadIdx.x;
    int b = idx >> 9;
    int c = idx & 511;
    int region = c >> 7;
    int off = c & 127;
    const float* tbl; int r;
    if (region == 0)      { tbl = et; r = seq[b]; }
    else if (region == 1) { tbl = ep; r = pos[b]; }
    else if (region == 2) { tbl = ey; r = yr[b]; }
    else                  { tbl = ei; r = fr[b]; }
    float4 v = ((const float4*)(tbl + (size_t)r * Hq))[off];
    ((float4*)g_x)[idx] = v;
}

// ---------------- tf32x3 tensor-core GEMM with cp.async pipeline ----------------
__device__ __forceinline__ uint32_t f2tf32(float x) {
    uint32_t r;
    asm("cvt.rna.tf32.f32 %0, %1;" : "=r"(r) : "f"(x));
    return r;
}
__device__ __forceinline__ void mma_tf32(float* d, const uint32_t* a, const uint32_t* b) {
    asm("mma.sync.aligned.m16n8k8.row.col.f32.tf32.tf32.f32 "
        "{%0,%1,%2,%3}, {%4,%5,%6,%7}, {%8,%9}, {%0,%1,%2,%3};"
        : "+f"(d[0]), "+f"(d[1]), "+f"(d[2]), "+f"(d[3])
        : "r"(a[0]), "r"(a[1]), "r"(a[2]), "r"(a[3]), "r"(b[0]), "r"(b[1]));
}
__device__ __forceinline__ void cp16(void* dst_smem, const void* src) {
    uint32_t d = (uint32_t)__cvta_generic_to_shared(dst_smem);
    asm volatile("cp.async.ca.shared.global [%0], [%1], 16;" :: "r"(d), "l"(src));
}
__device__ __forceinline__ void cp_commit() { asm volatile("cp.async.commit_group;"); }
template<int N> __device__ __forceinline__ void cp_wait() {
    asm volatile("cp.async.wait_group %0;" :: "n"(N));
}

#define LDA 20   // padded stride; conflict-free fragment reads

// C[128,N] = A[128,K] @ W[N,K]^T over k in [kstart, kstart+klen).
// part!=null -> write raw tile to part slab; else bias + C direct.
__device__ __forceinline__
void gemm_body(const float* __restrict__ A, int K,
               const float* __restrict__ W,
               const float* __restrict__ bias,
               float* __restrict__ C, int N,
               float* __restrict__ part,
               int nblk, int kstart, int klen)
{
    __shared__ float As[2][128 * LDA];
    __shared__ float Ws[2][128 * LDA];

    int t = threadIdx.x;
    int wid = t >> 5, lane = t & 31;
    int lr = lane >> 2, lc = lane & 3;
    int m0 = (wid & 3) * 32;
    int n0 = (wid >> 2) * 64;
    int r0 = t >> 2;            // stages rows r0, r0+64
    int k4 = (t & 3) * 4;

    float acc[2][8][4];
#pragma unroll
    for (int i = 0; i < 2; i++)
#pragma unroll
        for (int j = 0; j < 8; j++)
#pragma unroll
            for (int c = 0; c < 4; c++) acc[i][j][c] = 0.f;

    int nsteps = klen / 16;

#define STAGE(buf, kk)                                                              \
    do {                                                                            \
        cp16(&As[buf][r0 * LDA + k4],        A + (size_t)r0 * K + (kk) + k4);       \
        cp16(&As[buf][(r0 + 64) * LDA + k4], A + (size_t)(r0 + 64) * K + (kk) + k4);\
        cp16(&Ws[buf][r0 * LDA + k4],        W + (size_t)(nblk + r0) * K + (kk) + k4);\
        cp16(&Ws[buf][(r0 + 64) * LDA + k4], W + (size_t)(nblk + r0 + 64) * K + (kk) + k4);\
        cp_commit();                                                                \
    } while (0)

    STAGE(0, kstart);
    if (nsteps > 1) STAGE(1, kstart + 16);

    for (int i = 0; i < nsteps; i++) {
        if (i + 2 <= nsteps) cp_wait<1>(); else cp_wait<0>();
        __syncthreads();
        const float* Ab = As[i & 1];
        const float* Wb = Ws[i & 1];
#pragma unroll
        for (int ks = 0; ks < 2; ks++) {
            int k0 = ks * 8;
            uint32_t ah[2][4], al[2][4];
#pragma unroll
            for (int tt = 0; tt < 2; tt++) {
                int rb = m0 + tt * 16;
#pragma unroll
                for (int q = 0; q < 4; q++) {
                    int rr = rb + lr + (q & 1) * 8;
                    int cc = k0 + lc + (q >> 1) * 4;
                    float x = Ab[rr * LDA + cc];
                    uint32_t hi = f2tf32(x);
                    ah[tt][q] = hi;
                    al[tt][q] = f2tf32(x - __uint_as_float(hi));
                }
            }
#pragma unroll
            for (int j = 0; j < 8; j++) {
                int rn = (n0 + j * 8 + lr) * LDA;
                float x0 = Wb[rn + k0 + lc];
                float x1 = Wb[rn + k0 + lc + 4];
                uint32_t bh[2], bl[2];
                bh[0] = f2tf32(x0); bl[0] = f2tf32(x0 - __uint_as_float(bh[0]));
                bh[1] = f2tf32(x1); bl[1] = f2tf32(x1 - __uint_as_float(bh[1]));
#pragma unroll
                for (int tt = 0; tt < 2; tt++) {
                    mma_tf32(acc[tt][j], ah[tt], bh);
                    mma_tf32(acc[tt][j], ah[tt], bl);
                    mma_tf32(acc[tt][j], al[tt], bh);
                }
            }
        }
        __syncthreads();
        if (i + 2 < nsteps) STAGE(i & 1, kstart + (i + 2) * 16);
    }
#undef STAGE

    if (part) {
#pragma unroll
        for (int tt = 0; tt < 2; tt++)
#pragma unroll
            for (int j = 0; j < 8; j++) {
                int gr = m0 + tt * 16 + lr;
                int gc = nblk + n0 + j * 8 + 2 * lc;
                *(float2*)(part + (size_t)gr * N + gc) = make_float2(acc[tt][j][0], acc[tt][j][1]);
                *(float2*)(part + (size_t)(gr + 8) * N + gc) = make_float2(acc[tt][j][2], acc[tt][j][3]);
            }
    } else {
#pragma unroll
        for (int tt = 0; tt < 2; tt++)
#pragma unroll
            for (int j = 0; j < 8; j++) {
                int gr = m0 + tt * 16 + lr;
                int gc = nblk + n0 + j * 8 + 2 * lc;
                float b0 = bias ? bias[gc] : 0.f;
                float b1 = bias ? bias[gc + 1] : 0.f;
                *(float2*)(C + (size_t)gr * N + gc) = make_float2(acc[tt][j][0] + b0, acc[tt][j][1] + b1);
                *(float2*)(C + (size_t)(gr + 8) * N + gc) = make_float2(acc[tt][j][2] + b0, acc[tt][j][3] + b1);
            }
    }
}

// generic GEMM: grid (N/128, ksplit); ksplit>1 -> partial slabs in Cpart
__global__ __launch_bounds__(256, 2)
void gemm_tf32(const float* __restrict__ A, int K,
               const float* __restrict__ W,
               const float* __restrict__ bias,
               float* __restrict__ C, int N,
               float* __restrict__ Cpart)
{
    int ksplit = gridDim.y;
    int klen = K / ksplit;
    float* part = (ksplit > 1) ? (Cpart + (size_t)blockIdx.y * 128 * N) : nullptr;
    gemm_body(A, K, W, bias, C, N, part, blockIdx.x * 128, blockIdx.y * klen, klen);
}

// fused GRU GEMMs: grid (12, 8, 2); z=0 -> gx (K=4H), z=1 -> gh (K=H)
__global__ __launch_bounds__(256, 2)
void gemm_gru(const float* __restrict__ hprev,
              const float* __restrict__ W_ih, const float* __restrict__ W_hh)
{
    int N = 3 * Hq;
    if (blockIdx.z == 0) {
        int K = 4 * Hq, klen = K / 8;
        gemm_body(g_x, K, W_ih, nullptr, nullptr, N,
                  g_gemm_part + (size_t)blockIdx.y * 128 * N,
                  blockIdx.x * 128, blockIdx.y * klen, klen);
    } else {
        int K = Hq, klen = K / 8;
        gemm_body(hprev, K, W_hh, nullptr, nullptr, N,
                  g_gemm_part2 + (size_t)blockIdx.y * 128 * N,
                  blockIdx.x * 128, blockIdx.y * klen, klen);
    }
}

__global__ void reduce_split(const float* __restrict__ part, const float* __restrict__ bias,
                             float* __restrict__ C, int total, int N, int ksplit, int act)
{
    int idx = blockIdx.x * 256 + threadIdx.x;
    if (idx >= total) return;
    float s = 0.f;
    for (int z = 0; z < ksplit; z++) s += part[(size_t)z * total + idx];
    s += bias[idx % N];
    if (act == 1) s = tanhf(s);
    C[idx] = s;
}

// ---------------- fused split-K reduce + GRU gates ----------------
__global__ void gate_fused_kernel(const float* __restrict__ hprev,
                                  const float* __restrict__ b_ih,
                                  const float* __restrict__ b_hh,
                                  float* __restrict__ out_h)
{
    int idx = blockIdx.x * 256 + threadIdx.x;   // B*H
    int b = idx >> 9;
    int j = idx & 511;
    float xr = 0.f, xz = 0.f, xn = 0.f, hr = 0.f, hz = 0.f, hn = 0.f;
#pragma unroll
    for (int z = 0; z < 8; z++) {
        const float* P0 = g_gemm_part  + ((size_t)z * Bq + b) * (3 * Hq);
        const float* P1 = g_gemm_part2 + ((size_t)z * Bq + b) * (3 * Hq);
        xr += P0[j]; xz += P0[Hq + j]; xn += P0[2 * Hq + j];
        hr += P1[j]; hz += P1[Hq + j]; hn += P1[2 * Hq + j];
    }
    xr += b_ih[j]; xz += b_ih[Hq + j]; xn += b_ih[2 * Hq + j];
    hr += b_hh[j]; hz += b_hh[Hq + j]; hn += b_hh[2 * Hq + j];
    float r = 1.f / (1.f + __expf(-(xr + hr)));
    float z = 1.f / (1.f + __expf(-(xz + hz)));
    float n = tanhf(xn + r * hn);
    float hnew = (1.f - z) * n + z * hprev[idx];
    g_hnew[idx] = hnew;
    g_concat_in[(size_t)b * 2 * Hq + j] = hnew;
    if (out_h) out_h[idx] = hnew;
}

// ---------------- fused attention: single pass over enc ----------------
// 128-thread blocks for better wave packing (7 CTAs/SM, ~2.0 waves)
__global__ __launch_bounds__(128)
void attn_fused_kernel(const float* __restrict__ enc)
{
    int b = blockIdx.y;
    int t = threadIdx.x;
    int w = t >> 5;
    int lane = t & 31;
    int chunk = blockIdx.x * 4 + w;

    const float4* h4 = (const float4*)(g_hnew + (size_t)b * Hq);
    float4 h0 = h4[lane];
    float4 h1 = h4[lane + 32];
    float4 h2 = h4[lane + 64];
    float4 h3 = h4[lane + 96];

    float m = -1e30f, Z = 0.f;
    float4 c0 = make_float4(0.f,0.f,0.f,0.f), c1 = c0, c2 = c0, c3 = c0;

    int sbase = chunk * 64;
#pragma unroll 2
    for (int s0 = 0; s0 < 64; s0++) {
        int s = sbase + s0;
        const float4* e4 = (const float4*)(enc + ((size_t)s * Bq + b) * Hq);
        float4 e0 = e4[lane];
        float4 e1 = e4[lane + 32];
        float4 e2 = e4[lane + 64];
        float4 e3 = e4[lane + 96];
        float dp = e0.x*h0.x + e0.y*h0.y + e0.z*h0.z + e0.w*h0.w
                 + e1.x*h1.x + e1.y*h1.y + e1.z*h1.z + e1.w*h1.w
                 + e2.x*h2.x + e2.y*h2.y + e2.z*h2.z + e2.w*h2.w
                 + e3.x*h3.x + e3.y*h3.y + e3.z*h3.z + e3.w*h3.w;
#pragma unroll
        for (int off = 16; off > 0; off >>= 1)
            dp += __shfl_xor_sync(0xffffffffu, dp, off);
        if (lane == 0) g_scores[(size_t)b * Sq + s] = dp;
        if (dp <= m) {                       // warp-uniform: no divergence
            float p = __expf(dp - m);
            Z += p;
            c0.x += p*e0.x; c0.y += p*e0.y; c0.z += p*e0.z; c0.w += p*e0.w;
            c1.x += p*e1.x; c1.y += p*e1.y; c1.z += p*e1.z; c1.w += p*e1.w;
            c2.x += p*e2.x; c2.y += p*e2.y; c2.z += p*e2.z; c2.w += p*e2.w;
            c3.x += p*e3.x; c3.y += p*e3.y; c3.z += p*e3.z; c3.w += p*e3.w;
        } else {                             // rare: new max
            float corr = __expf(m - dp);
            Z = Z * corr + 1.f;
            c0.x = c0.x*corr + e0.x; c0.y = c0.y*corr + e0.y; c0.z = c0.z*corr + e0.z; c0.w = c0.w*corr + e0.w;
            c1.x = c1.x*corr + e1.x; c1.y = c1.y*corr + e1.y; c1.z = c1.z*corr + e1.z; c1.w = c1.w*corr + e1.w;
            c2.x = c2.x*corr + e2.x; c2.y = c2.y*corr + e2.y; c2.z = c2.z*corr + e2.z; c2.w = c2.w*corr + e2.w;
            c3.x = c3.x*corr + e3.x; c3.y = c3.y*corr + e3.y; c3.z = c3.z*corr + e3.z; c3.w = c3.w*corr + e3.w;
            m = dp;
        }
    }

    int pc = b * NCHUNK + chunk;
    float4* pctx = (float4*)(g_pctx + (size_t)pc * Hq);
    pctx[lane]      = c0;
    pctx[lane + 32] = c1;
    pctx[lane + 64] = c2;
    pctx[lane + 96] = c3;
    if (lane == 0) { g_pm[pc] = m; g_pz[pc] = Z; }
}

// ---------------- combine partials -> context + write attn weights ----------------
__global__ __launch_bounds__(128)
void attn_reduce_kernel(float* __restrict__ out_attn)
{
    __shared__ float scale[NCHUNK];
    __shared__ float sm[NCHUNK];
    __shared__ float sz[NCHUNK];
    __shared__ float sM, sZinv;
    int b = blockIdx.x;
    int t = threadIdx.x;
    if (t < NCHUNK) { sm[t] = g_pm[b * NCHUNK + t]; sz[t] = g_pz[b * NCHUNK + t]; }
    __syncthreads();
    if (t == 0) {
        float M = -1e30f;
        for (int c = 0; c < NCHUNK; c++) M = fmaxf(M, sm[c]);
        float Zt = 0.f;
        for (int c = 0; c < NCHUNK; c++) {
            float sc = __expf(sm[c] - M);
            scale[c] = sc;
            Zt += sz[c] * sc;
        }
        sM = M;
        sZinv = 1.f / Zt;
    }
    __syncthreads();
    float zinv = sZinv;
    float M = sM;
    float a0 = 0.f, a1 = 0.f, a2 = 0.f, a3 = 0.f;
    for (int c = 0; c < NCHUNK; c++) {
        const float4 v = *(const float4*)(g_pctx + ((size_t)(b * NCHUNK + c)) * Hq + t * 4);
        float sc = scale[c];
        a0 += v.x * sc; a1 += v.y * sc; a2 += v.z * sc; a3 += v.w * sc;
    }
    float4 r = make_float4(a0 * zinv, a1 * zinv, a2 * zinv, a3 * zinv);
    *(float4*)(g_concat_in + (size_t)b * 2 * Hq + Hq + t * 4) = r;

    if (out_attn) {
        const float* sc_row = g_scores + (size_t)b * Sq;
        float* out_row = out_attn + (size_t)b * Sq;
        for (int i = t; i < Sq; i += 128)
            out_row[i] = __expf(sc_row[i] - M) * zinv;
    }
}

// ---------------- launch ----------------
extern "C" void kernel_launch(void* const* d_in, const int* in_sizes, int n_in,
                              void* d_out, int out_size)
{
    const int* input_seq   = (const int*)d_in[0];
    const int* positions   = (const int*)d_in[1];
    const int* years       = (const int*)d_in[2];
    const int* froms       = (const int*)d_in[3];
    const float* last_h    = (const float*)d_in[4];
    const float* enc       = (const float*)d_in[5];
    const float* emb_tok   = (const float*)d_in[6];
    const float* emb_pos   = (const float*)d_in[7];
    const float* emb_year  = (const float*)d_in[8];
    const float* emb_inst  = (const float*)d_in[9];
    const float* W_ih      = (const float*)d_in[10];
    const float* b_ih      = (const float*)d_in[11];
    const float* W_hh      = (const float*)d_in[12];
    const float* b_hh      = (const float*)d_in[13];
    const float* W_concat  = (const float*)d_in[14];
    const float* b_concat  = (const float*)d_in[15];
    const float* W_out     = (const float*)d_in[16];
    const float* b_out     = (const float*)d_in[17];

    float* out = (float*)d_out;
    float* out_logits = out;
    float* out_h = nullptr;
    float* out_attn = nullptr;
    long long need = (long long)Bq * Vq + (long long)Bq * Hq + (long long)Bq * Sq;
    if ((long long)out_size >= need) {
        out_h = out + (size_t)Bq * Vq;
        out_attn = out_h + (size_t)Bq * Hq;
    }

    float *part, *concat_in, *concat_out;
    cudaGetSymbolAddress((void**)&part, g_gemm_part);
    cudaGetSymbolAddress((void**)&concat_in, g_concat_in);
    cudaGetSymbolAddress((void**)&concat_out, g_concat_out);

    // 1. embeddings -> x [B,4H]
    embed_kernel<<<256, 256>>>(input_seq, positions, years, froms,
                               emb_tok, emb_pos, emb_year, emb_inst);
    // 2. gx AND gh in one launch (split-K 8 each, partials)
    gemm_gru<<<dim3(12, 8, 2), 256>>>(last_h, W_ih, W_hh);
    // 3. fused split-K reduce + gates -> h_new
    gate_fused_kernel<<<(Bq * Hq) / 256, 256>>>(last_h, b_ih, b_hh, out_h);
    // 4. fused scores + online-softmax context (single pass over enc)
    attn_fused_kernel<<<dim3(16, Bq), 128>>>(enc);
    // 5. combine partials -> context + attn weights output
    attn_reduce_kernel<<<Bq, 128>>>(out_attn);
    // 6. concat_out = tanh(concat_in @ W_concat^T + b_concat) (split-K 8)
    gemm_tf32<<<dim3(4, 8), 256>>>(concat_in, 2 * Hq, W_concat, nullptr, nullptr, Hq, part);
    reduce_split<<<(Bq * Hq + 255) / 256, 256>>>(part, b_concat, concat_out, Bq * Hq, Hq, 8, 1);
    // 7. logits = concat_out @ W_out^T + b_out  (split-K 1, bias fused, direct out)
    gemm_tf32<<<dim3(Vq / 128, 1), 256>>>(concat_out, Hq, W_out, b_out, out_logits, Vq, nullptr);
}

// round 7
// speedup vs baseline: 1.7247x; 1.0600x over previous
#include <cuda_runtime.h>
#include <cuda_bf16.h>
#include <math.h>
#include <stdint.h>

#define Bq 128
#define Sq 4096
#define Hq 512
#define Vq 32000
#define NCHUNK 64

// ---------------- scratch (no allocations allowed) ----------------
__device__ float g_x[Bq * 4 * Hq];
__device__ float g_hnew[Bq * Hq];
__device__ float g_scores[Bq * Sq];
__device__ float g_pm[Bq * NCHUNK];
__device__ float g_pz[Bq * NCHUNK];
__device__ float g_pctx[Bq * NCHUNK * Hq];
__device__ float g_concat_in[Bq * 2 * Hq];
__device__ float g_concat_out[Bq * Hq];
__device__ float g_gemm_part [8 * Bq * 3 * Hq];
__device__ float g_gemm_part2[8 * Bq * 3 * Hq];

// ---------------- embedding gather ----------------
__global__ void embed_kernel(const int* __restrict__ seq, const int* __restrict__ pos,
                             const int* __restrict__ yr, const int* __restrict__ fr,
                             const float* __restrict__ et, const float* __restrict__ ep,
                             const float* __restrict__ ey, const float* __restrict__ ei)
{
    int idx = blockIdx.x * 256 + threadIdx.x;
    int b = idx >> 9;
    int c = idx & 511;
    int region = c >> 7;
    int off = c & 127;
    const float* tbl; int r;
    if (region == 0)      { tbl = et; r = seq[b]; }
    else if (region == 1) { tbl = ep; r = pos[b]; }
    else if (region == 2) { tbl = ey; r = yr[b]; }
    else                  { tbl = ei; r = fr[b]; }
    float4 v = ((const float4*)(tbl + (size_t)r * Hq))[off];
    ((float4*)g_x)[idx] = v;
}

// ---------------- tf32 tensor-core GEMM, 3-deep cp.async ring ----------------
__device__ __forceinline__ uint32_t f2tf32(float x) {
    uint32_t r;
    asm("cvt.rna.tf32.f32 %0, %1;" : "=r"(r) : "f"(x));
    return r;
}
__device__ __forceinline__ void mma_tf32(float* d, const uint32_t* a, const uint32_t* b) {
    asm("mma.sync.aligned.m16n8k8.row.col.f32.tf32.tf32.f32 "
        "{%0,%1,%2,%3}, {%4,%5,%6,%7}, {%8,%9}, {%0,%1,%2,%3};"
        : "+f"(d[0]), "+f"(d[1]), "+f"(d[2]), "+f"(d[3])
        : "r"(a[0]), "r"(a[1]), "r"(a[2]), "r"(a[3]), "r"(b[0]), "r"(b[1]));
}
__device__ __forceinline__ void cp16(void* dst_smem, const void* src) {
    uint32_t d = (uint32_t)__cvta_generic_to_shared(dst_smem);
    asm volatile("cp.async.ca.shared.global [%0], [%1], 16;" :: "r"(d), "l"(src));
}
__device__ __forceinline__ void cp_commit() { asm volatile("cp.async.commit_group;"); }
template<int N> __device__ __forceinline__ void cp_wait() {
    asm volatile("cp.async.wait_group %0;" :: "n"(N));
}

#define LDA 20
#define TILE_F (128 * LDA)                 // floats per stage tile
#define GEMM_SMEM_BYTES (3 * 2 * TILE_F * 4)  // 3 stages x (A + W)

// C[128,N] = A[128,K] @ W[N,K]^T over k in [kstart, kstart+klen).
// prec: 3 -> tf32x3 (fp32-grade), 2 -> tf32x2 (~2e-4 rel)
__device__ __forceinline__
void gemm_body(const float* __restrict__ A, int K,
               const float* __restrict__ W,
               const float* __restrict__ bias,
               float* __restrict__ C, int N,
               float* __restrict__ part,
               int nblk, int kstart, int klen, int prec)
{
    extern __shared__ float sm[];
    float* Asm = sm;                // 3 stages of A
    float* Wsm = sm + 3 * TILE_F;   // 3 stages of W

    int t = threadIdx.x;
    int wid = t >> 5, lane = t & 31;
    int lr = lane >> 2, lc = lane & 3;
    int m0 = (wid & 3) * 32;
    int n0 = (wid >> 2) * 64;
    int r0 = t >> 2;
    int k4 = (t & 3) * 4;

    float acc[2][8][4];
#pragma unroll
    for (int i = 0; i < 2; i++)
#pragma unroll
        for (int j = 0; j < 8; j++)
#pragma unroll
            for (int c = 0; c < 4; c++) acc[i][j][c] = 0.f;

    int nsteps = klen / 16;

#define STAGE(buf, kk)                                                                 \
    do {                                                                               \
        float* Ad = Asm + (buf) * TILE_F;                                              \
        float* Wd = Wsm + (buf) * TILE_F;                                              \
        cp16(Ad + r0 * LDA + k4,        A + (size_t)r0 * K + (kk) + k4);               \
        cp16(Ad + (r0 + 64) * LDA + k4, A + (size_t)(r0 + 64) * K + (kk) + k4);        \
        cp16(Wd + r0 * LDA + k4,        W + (size_t)(nblk + r0) * K + (kk) + k4);      \
        cp16(Wd + (r0 + 64) * LDA + k4, W + (size_t)(nblk + r0 + 64) * K + (kk) + k4); \
        cp_commit();                                                                   \
    } while (0)

#pragma unroll
    for (int p = 0; p < 3; p++) {
        if (p < nsteps) STAGE(p, kstart + p * 16);
        else cp_commit();
    }

    for (int i = 0; i < nsteps; i++) {
        cp_wait<2>();
        __syncthreads();
        int buf = i % 3;
        const float* Ab = Asm + buf * TILE_F;
        const float* Wb = Wsm + buf * TILE_F;
#pragma unroll
        for (int ks = 0; ks < 2; ks++) {
            int k0 = ks * 8;
            uint32_t ah[2][4], al[2][4];
#pragma unroll
            for (int tt = 0; tt < 2; tt++) {
                int rb = m0 + tt * 16;
#pragma unroll
                for (int q = 0; q < 4; q++) {
                    int rr = rb + lr + (q & 1) * 8;
                    int cc = k0 + lc + (q >> 1) * 4;
                    float x = Ab[rr * LDA + cc];
                    uint32_t hi = f2tf32(x);
                    ah[tt][q] = hi;
                    if (prec == 3) al[tt][q] = f2tf32(x - __uint_as_float(hi));
                }
            }
#pragma unroll
            for (int j = 0; j < 8; j++) {
                int rn = (n0 + j * 8 + lr) * LDA;
                float x0 = Wb[rn + k0 + lc];
                float x1 = Wb[rn + k0 + lc + 4];
                uint32_t bh[2], bl[2];
                bh[0] = f2tf32(x0); bl[0] = f2tf32(x0 - __uint_as_float(bh[0]));
                bh[1] = f2tf32(x1); bl[1] = f2tf32(x1 - __uint_as_float(bh[1]));
#pragma unroll
                for (int tt = 0; tt < 2; tt++) {
                    mma_tf32(acc[tt][j], ah[tt], bh);
                    mma_tf32(acc[tt][j], ah[tt], bl);
                    if (prec == 3) mma_tf32(acc[tt][j], al[tt], bh);
                }
            }
        }
        __syncthreads();
        int nx = i + 3;
        if (nx < nsteps) STAGE(buf, kstart + nx * 16);
        else cp_commit();
    }
#undef STAGE

    if (part) {
#pragma unroll
        for (int tt = 0; tt < 2; tt++)
#pragma unroll
            for (int j = 0; j < 8; j++) {
                int gr = m0 + tt * 16 + lr;
                int gc = nblk + n0 + j * 8 + 2 * lc;
                *(float2*)(part + (size_t)gr * N + gc) = make_float2(acc[tt][j][0], acc[tt][j][1]);
                *(float2*)(part + (size_t)(gr + 8) * N + gc) = make_float2(acc[tt][j][2], acc[tt][j][3]);
            }
    } else {
#pragma unroll
        for (int tt = 0; tt < 2; tt++)
#pragma unroll
            for (int j = 0; j < 8; j++) {
                int gr = m0 + tt * 16 + lr;
                int gc = nblk + n0 + j * 8 + 2 * lc;
                float b0 = bias ? bias[gc] : 0.f;
                float b1 = bias ? bias[gc + 1] : 0.f;
                *(float2*)(C + (size_t)gr * N + gc) = make_float2(acc[tt][j][0] + b0, acc[tt][j][1] + b1);
                *(float2*)(C + (size_t)(gr + 8) * N + gc) = make_float2(acc[tt][j][2] + b0, acc[tt][j][3] + b1);
            }
    }
}

__global__ __launch_bounds__(256, 2)
void gemm_tf32(const float* __restrict__ A, int K,
               const float* __restrict__ W,
               const float* __restrict__ bias,
               float* __restrict__ C, int N,
               float* __restrict__ Cpart, int prec)
{
    int ksplit = gridDim.y;
    int klen = K / ksplit;
    float* part = (ksplit > 1) ? (Cpart + (size_t)blockIdx.y * 128 * N) : nullptr;
    gemm_body(A, K, W, bias, C, N, part, blockIdx.x * 128, blockIdx.y * klen, klen, prec);
}

// fused GRU GEMMs: grid (12, 8, 2); z=0 -> gx (K=4H), z=1 -> gh (K=H)
__global__ __launch_bounds__(256, 2)
void gemm_gru(const float* __restrict__ hprev,
              const float* __restrict__ W_ih, const float* __restrict__ W_hh)
{
    int N = 3 * Hq;
    if (blockIdx.z == 0) {
        int K = 4 * Hq, klen = K / 8;
        gemm_body(g_x, K, W_ih, nullptr, nullptr, N,
                  g_gemm_part + (size_t)blockIdx.y * 128 * N,
                  blockIdx.x * 128, blockIdx.y * klen, klen, 3);
    } else {
        int K = Hq, klen = K / 8;
        gemm_body(hprev, K, W_hh, nullptr, nullptr, N,
                  g_gemm_part2 + (size_t)blockIdx.y * 128 * N,
                  blockIdx.x * 128, blockIdx.y * klen, klen, 3);
    }
}

__global__ void reduce_split(const float* __restrict__ part, const float* __restrict__ bias,
                             float* __restrict__ C, int total, int N, int ksplit, int act)
{
    int idx = blockIdx.x * 256 + threadIdx.x;
    if (idx >= total) return;
    float s = 0.f;
    for (int z = 0; z < ksplit; z++) s += part[(size_t)z * total + idx];
    s += bias[idx % N];
    if (act == 1) s = tanhf(s);
    C[idx] = s;
}

// ---------------- fused split-K reduce + GRU gates ----------------
__global__ void gate_fused_kernel(const float* __restrict__ hprev,
                                  const float* __restrict__ b_ih,
                                  const float* __restrict__ b_hh,
                                  float* __restrict__ out_h)
{
    int idx = blockIdx.x * 256 + threadIdx.x;
    int b = idx >> 9;
    int j = idx & 511;
    float xr = 0.f, xz = 0.f, xn = 0.f, hr = 0.f, hz = 0.f, hn = 0.f;
#pragma unroll
    for (int z = 0; z < 8; z++) {
        const float* P0 = g_gemm_part  + ((size_t)z * Bq + b) * (3 * Hq);
        const float* P1 = g_gemm_part2 + ((size_t)z * Bq + b) * (3 * Hq);
        xr += P0[j]; xz += P0[Hq + j]; xn += P0[2 * Hq + j];
        hr += P1[j]; hz += P1[Hq + j]; hn += P1[2 * Hq + j];
    }
    xr += b_ih[j]; xz += b_ih[Hq + j]; xn += b_ih[2 * Hq + j];
    hr += b_hh[j]; hz += b_hh[Hq + j]; hn += b_hh[2 * Hq + j];
    float r = 1.f / (1.f + __expf(-(xr + hr)));
    float z = 1.f / (1.f + __expf(-(xz + hz)));
    float n = tanhf(xn + r * hn);
    float hnew = (1.f - z) * n + z * hprev[idx];
    g_hnew[idx] = hnew;
    g_concat_in[(size_t)b * 2 * Hq + j] = hnew;
    if (out_h) out_h[idx] = hnew;
}

// ---------------- fused attention: single pass over enc ----------------
__global__ __launch_bounds__(128)
void attn_fused_kernel(const float* __restrict__ enc)
{
    int b = blockIdx.y;
    int t = threadIdx.x;
    int w = t >> 5;
    int lane = t & 31;
    int chunk = blockIdx.x * 4 + w;

    const float4* h4 = (const float4*)(g_hnew + (size_t)b * Hq);
    float4 h0 = h4[lane];
    float4 h1 = h4[lane + 32];
    float4 h2 = h4[lane + 64];
    float4 h3 = h4[lane + 96];

    float m = -1e30f, Z = 0.f;
    float4 c0 = make_float4(0.f,0.f,0.f,0.f), c1 = c0, c2 = c0, c3 = c0;

    int sbase = chunk * 64;
#pragma unroll 2
    for (int s0 = 0; s0 < 64; s0++) {
        int s = sbase + s0;
        const float4* e4 = (const float4*)(enc + ((size_t)s * Bq + b) * Hq);
        float4 e0 = e4[lane];
        float4 e1 = e4[lane + 32];
        float4 e2 = e4[lane + 64];
        float4 e3 = e4[lane + 96];
        float dp = e0.x*h0.x + e0.y*h0.y + e0.z*h0.z + e0.w*h0.w
                 + e1.x*h1.x + e1.y*h1.y + e1.z*h1.z + e1.w*h1.w
                 + e2.x*h2.x + e2.y*h2.y + e2.z*h2.z + e2.w*h2.w
                 + e3.x*h3.x + e3.y*h3.y + e3.z*h3.z + e3.w*h3.w;
#pragma unroll
        for (int off = 16; off > 0; off >>= 1)
            dp += __shfl_xor_sync(0xffffffffu, dp, off);
        if (lane == 0) g_scores[(size_t)b * Sq + s] = dp;
        if (dp <= m) {
            float p = __expf(dp - m);
            Z += p;
            c0.x += p*e0.x; c0.y += p*e0.y; c0.z += p*e0.z; c0.w += p*e0.w;
            c1.x += p*e1.x; c1.y += p*e1.y; c1.z += p*e1.z; c1.w += p*e1.w;
            c2.x += p*e2.x; c2.y += p*e2.y; c2.z += p*e2.z; c2.w += p*e2.w;
            c3.x += p*e3.x; c3.y += p*e3.y; c3.z += p*e3.z; c3.w += p*e3.w;
        } else {
            float corr = __expf(m - dp);
            Z = Z * corr + 1.f;
            c0.x = c0.x*corr + e0.x; c0.y = c0.y*corr + e0.y; c0.z = c0.z*corr + e0.z; c0.w = c0.w*corr + e0.w;
            c1.x = c1.x*corr + e1.x; c1.y = c1.y*corr + e1.y; c1.z = c1.z*corr + e1.z; c1.w = c1.w*corr + e1.w;
            c2.x = c2.x*corr + e2.x; c2.y = c2.y*corr + e2.y; c2.z = c2.z*corr + e2.z; c2.w = c2.w*corr + e2.w;
            c3.x = c3.x*corr + e3.x; c3.y = c3.y*corr + e3.y; c3.z = c3.z*corr + e3.z; c3.w = c3.w*corr + e3.w;
            m = dp;
        }
    }

    int pc = b * NCHUNK + chunk;
    float4* pctx = (float4*)(g_pctx + (size_t)pc * Hq);
    pctx[lane]      = c0;
    pctx[lane + 32] = c1;
    pctx[lane + 64] = c2;
    pctx[lane + 96] = c3;
    if (lane == 0) { g_pm[pc] = m; g_pz[pc] = Z; }
}

// ---------------- combine partials -> context + write attn weights ----------------
__global__ __launch_bounds__(128)
void attn_reduce_kernel(float* __restrict__ out_attn)
{
    __shared__ float scale[NCHUNK];
    __shared__ float smx[NCHUNK];
    __shared__ float szz[NCHUNK];
    __shared__ float sM, sZinv;
    int b = blockIdx.x;
    int t = threadIdx.x;
    if (t < NCHUNK) { smx[t] = g_pm[b * NCHUNK + t]; szz[t] = g_pz[b * NCHUNK + t]; }
    __syncthreads();
    if (t == 0) {
        float M = -1e30f;
        for (int c = 0; c < NCHUNK; c++) M = fmaxf(M, smx[c]);
        float Zt = 0.f;
        for (int c = 0; c < NCHUNK; c++) {
            float sc = __expf(smx[c] - M);
            scale[c] = sc;
            Zt += szz[c] * sc;
        }
        sM = M;
        sZinv = 1.f / Zt;
    }
    __syncthreads();
    float zinv = sZinv;
    float M = sM;
    float a0 = 0.f, a1 = 0.f, a2 = 0.f, a3 = 0.f;
    for (int c = 0; c < NCHUNK; c++) {
        const float4 v = *(const float4*)(g_pctx + ((size_t)(b * NCHUNK + c)) * Hq + t * 4);
        float sc = scale[c];
        a0 += v.x * sc; a1 += v.y * sc; a2 += v.z * sc; a3 += v.w * sc;
    }
    float4 r = make_float4(a0 * zinv, a1 * zinv, a2 * zinv, a3 * zinv);
    *(float4*)(g_concat_in + (size_t)b * 2 * Hq + Hq + t * 4) = r;

    if (out_attn) {
        const float* sc_row = g_scores + (size_t)b * Sq;
        float* out_row = out_attn + (size_t)b * Sq;
        for (int i = t; i < Sq; i += 128)
            out_row[i] = __expf(sc_row[i] - M) * zinv;
    }
}

// ---------------- launch ----------------
extern "C" void kernel_launch(void* const* d_in, const int* in_sizes, int n_in,
                              void* d_out, int out_size)
{
    const int* input_seq   = (const int*)d_in[0];
    const int* positions   = (const int*)d_in[1];
    const int* years       = (const int*)d_in[2];
    const int* froms       = (const int*)d_in[3];
    const float* last_h    = (const float*)d_in[4];
    const float* enc       = (const float*)d_in[5];
    const float* emb_tok   = (const float*)d_in[6];
    const float* emb_pos   = (const float*)d_in[7];
    const float* emb_year  = (const float*)d_in[8];
    const float* emb_inst  = (const float*)d_in[9];
    const float* W_ih      = (const float*)d_in[10];
    const float* b_ih      = (const float*)d_in[11];
    const float* W_hh      = (const float*)d_in[12];
    const float* b_hh      = (const float*)d_in[13];
    const float* W_concat  = (const float*)d_in[14];
    const float* b_concat  = (const float*)d_in[15];
    const float* W_out     = (const float*)d_in[16];
    const float* b_out     = (const float*)d_in[17];

    float* out = (float*)d_out;
    float* out_logits = out;
    float* out_h = nullptr;
    float* out_attn = nullptr;
    long long need = (long long)Bq * Vq + (long long)Bq * Hq + (long long)Bq * Sq;
    if ((long long)out_size >= need) {
        out_h = out + (size_t)Bq * Vq;
        out_attn = out_h + (size_t)Bq * Hq;
    }

    float *part, *concat_in, *concat_out;
    cudaGetSymbolAddress((void**)&part, g_gemm_part);
    cudaGetSymbolAddress((void**)&concat_in, g_concat_in);
    cudaGetSymbolAddress((void**)&concat_out, g_concat_out);

    static int smem_set = 0;
    if (!smem_set) {
        cudaFuncSetAttribute(gemm_tf32, cudaFuncAttributeMaxDynamicSharedMemorySize, GEMM_SMEM_BYTES);
        cudaFuncSetAttribute(gemm_gru, cudaFuncAttributeMaxDynamicSharedMemorySize, GEMM_SMEM_BYTES);
        smem_set = 1;
    }

    // 1. embeddings -> x [B,4H]
    embed_kernel<<<256, 256>>>(input_seq, positions, years, froms,
                               emb_tok, emb_pos, emb_year, emb_inst);
    // 2. gx AND gh in one launch (split-K 8 each, tf32x3 partials)
    gemm_gru<<<dim3(12, 8, 2), 256, GEMM_SMEM_BYTES>>>(last_h, W_ih, W_hh);
    // 3. fused split-K reduce + gates -> h_new
    gate_fused_kernel<<<(Bq * Hq) / 256, 256>>>(last_h, b_ih, b_hh, out_h);
    // 4. fused scores + online-softmax context (single pass over enc)
    attn_fused_kernel<<<dim3(16, Bq), 128>>>(enc);
    // 5. combine partials -> context + attn weights output
    attn_reduce_kernel<<<Bq, 128>>>(out_attn);
    // 6. concat_out = tanh(concat_in @ W_concat^T + b_concat) (tf32x3, split-K 8)
    gemm_tf32<<<dim3(4, 8), 256, GEMM_SMEM_BYTES>>>(concat_in, 2 * Hq, W_concat, nullptr, nullptr, Hq, part, 3);
    reduce_split<<<(Bq * Hq + 255) / 256, 256>>>(part, b_concat, concat_out, Bq * Hq, Hq, 8, 1);
    // 7. logits = concat_out @ W_out^T + b_out  (tf32x2, split-K 1, direct out)
    gemm_tf32<<<dim3(Vq / 128, 1), 256, GEMM_SMEM_BYTES>>>(concat_out, Hq, W_out, b_out, out_logits, Vq, nullptr, 2);
}

// round 8
// speedup vs baseline: 1.7497x; 1.0145x over previous
#include <cuda_runtime.h>
#include <cuda_bf16.h>
#include <math.h>
#include <stdint.h>

#define Bq 128
#define Sq 4096
#define Hq 512
#define Vq 32000
#define NCHUNK 64

// ---------------- scratch (no allocations allowed) ----------------
__device__ float g_hnew[Bq * Hq];
__device__ float g_scores[Bq * Sq];
__device__ float g_pm[Bq * NCHUNK];
__device__ float g_pz[Bq * NCHUNK];
__device__ float g_pctx[Bq * NCHUNK * Hq];
__device__ float g_concat_in[Bq * 2 * Hq];
__device__ float g_concat_out[Bq * Hq];
__device__ float g_gemm_part [8 * Bq * 3 * Hq];
__device__ float g_gemm_part2[8 * Bq * 3 * Hq];

// ---------------- tf32 tensor-core GEMM, 3-deep cp.async ring ----------------
__device__ __forceinline__ uint32_t f2tf32(float x) {
    uint32_t r;
    asm("cvt.rna.tf32.f32 %0, %1;" : "=r"(r) : "f"(x));
    return r;
}
__device__ __forceinline__ void mma_tf32(float* d, const uint32_t* a, const uint32_t* b) {
    asm("mma.sync.aligned.m16n8k8.row.col.f32.tf32.tf32.f32 "
        "{%0,%1,%2,%3}, {%4,%5,%6,%7}, {%8,%9}, {%0,%1,%2,%3};"
        : "+f"(d[0]), "+f"(d[1]), "+f"(d[2]), "+f"(d[3])
        : "r"(a[0]), "r"(a[1]), "r"(a[2]), "r"(a[3]), "r"(b[0]), "r"(b[1]));
}
__device__ __forceinline__ void cp16(void* dst_smem, const void* src) {
    uint32_t d = (uint32_t)__cvta_generic_to_shared(dst_smem);
    asm volatile("cp.async.ca.shared.global [%0], [%1], 16;" :: "r"(d), "l"(src));
}
__device__ __forceinline__ void cp_commit() { asm volatile("cp.async.commit_group;"); }
template<int N> __device__ __forceinline__ void cp_wait() {
    asm volatile("cp.async.wait_group %0;" :: "n"(N));
}

#define LDA 20
#define TILE_F (128 * LDA)
#define GEMM_SMEM_BYTES (3 * 2 * TILE_F * 4)

// C[128,N](cols nblk..nblk+127) += sum over nsteps k-tiles of 16.
// aptr0/aptr1: global sources for A rows r0, r0+64 at this thread's k4 offset.
// wptr0/wptr1: same for W rows nblk+r0, nblk+r0+64. All advance +16 floats/step.
// prec: 3 -> tf32x3 (fp32-grade), 2 -> tf32x2 (~2e-4)
__device__ __forceinline__
void gemm_body(const float* aptr0, const float* aptr1,
               const float* wptr0, const float* wptr1,
               const float* __restrict__ bias,
               float* __restrict__ C, int N,
               float* __restrict__ part,
               int nblk, int nsteps, int prec)
{
    extern __shared__ float smx[];
    float* Asm = smx;
    float* Wsm = smx + 3 * TILE_F;

    int t = threadIdx.x;
    int wid = t >> 5, lane = t & 31;
    int lr = lane >> 2, lc = lane & 3;
    int m0 = (wid & 3) * 32;
    int n0 = (wid >> 2) * 64;
    int r0 = t >> 2;
    int k4 = (t & 3) * 4;

    float acc[2][8][4];
#pragma unroll
    for (int i = 0; i < 2; i++)
#pragma unroll
        for (int j = 0; j < 8; j++)
#pragma unroll
            for (int c = 0; c < 4; c++) acc[i][j][c] = 0.f;

#define STAGE(buf, step)                                              \
    do {                                                              \
        float* Ad = Asm + (buf) * TILE_F;                             \
        float* Wd = Wsm + (buf) * TILE_F;                             \
        cp16(Ad + r0 * LDA + k4,        aptr0 + (step) * 16);         \
        cp16(Ad + (r0 + 64) * LDA + k4, aptr1 + (step) * 16);         \
        cp16(Wd + r0 * LDA + k4,        wptr0 + (step) * 16);         \
        cp16(Wd + (r0 + 64) * LDA + k4, wptr1 + (step) * 16);         \
        cp_commit();                                                  \
    } while (0)

#pragma unroll
    for (int p = 0; p < 3; p++) {
        if (p < nsteps) STAGE(p, p);
        else cp_commit();
    }

    for (int i = 0; i < nsteps; i++) {
        cp_wait<2>();
        __syncthreads();
        int buf = i % 3;
        const float* Ab = Asm + buf * TILE_F;
        const float* Wb = Wsm + buf * TILE_F;
#pragma unroll
        for (int ks = 0; ks < 2; ks++) {
            int k0 = ks * 8;
            uint32_t ah[2][4], al[2][4];
#pragma unroll
            for (int tt = 0; tt < 2; tt++) {
                int rb = m0 + tt * 16;
#pragma unroll
                for (int q = 0; q < 4; q++) {
                    int rr = rb + lr + (q & 1) * 8;
                    int cc = k0 + lc + (q >> 1) * 4;
                    float x = Ab[rr * LDA + cc];
                    uint32_t hi = f2tf32(x);
                    ah[tt][q] = hi;
                    if (prec == 3) al[tt][q] = f2tf32(x - __uint_as_float(hi));
                }
            }
#pragma unroll
            for (int j = 0; j < 8; j++) {
                int rn = (n0 + j * 8 + lr) * LDA;
                float x0 = Wb[rn + k0 + lc];
                float x1 = Wb[rn + k0 + lc + 4];
                uint32_t bh[2], bl[2];
                bh[0] = f2tf32(x0); bl[0] = f2tf32(x0 - __uint_as_float(bh[0]));
                bh[1] = f2tf32(x1); bl[1] = f2tf32(x1 - __uint_as_float(bh[1]));
#pragma unroll
                for (int tt = 0; tt < 2; tt++) {
                    mma_tf32(acc[tt][j], ah[tt], bh);
                    mma_tf32(acc[tt][j], ah[tt], bl);
                    if (prec == 3) mma_tf32(acc[tt][j], al[tt], bh);
                }
            }
        }
        __syncthreads();
        int nx = i + 3;
        if (nx < nsteps) STAGE(buf, nx);
        else cp_commit();
    }
#undef STAGE

    if (part) {
#pragma unroll
        for (int tt = 0; tt < 2; tt++)
#pragma unroll
            for (int j = 0; j < 8; j++) {
                int gr = m0 + tt * 16 + lr;
                int gc = nblk + n0 + j * 8 + 2 * lc;
                *(float2*)(part + (size_t)gr * N + gc) = make_float2(acc[tt][j][0], acc[tt][j][1]);
                *(float2*)(part + (size_t)(gr + 8) * N + gc) = make_float2(acc[tt][j][2], acc[tt][j][3]);
            }
    } else {
#pragma unroll
        for (int tt = 0; tt < 2; tt++)
#pragma unroll
            for (int j = 0; j < 8; j++) {
                int gr = m0 + tt * 16 + lr;
                int gc = nblk + n0 + j * 8 + 2 * lc;
                float b0 = bias ? bias[gc] : 0.f;
                float b1 = bias ? bias[gc + 1] : 0.f;
                *(float2*)(C + (size_t)gr * N + gc) = make_float2(acc[tt][j][0] + b0, acc[tt][j][1] + b1);
                *(float2*)(C + (size_t)(gr + 8) * N + gc) = make_float2(acc[tt][j][2] + b0, acc[tt][j][3] + b1);
            }
    }
}

// generic GEMM: C[128,N] = A[128,K] @ W[N,K]^T, grid (N/128, ksplit)
__global__ __launch_bounds__(256, 2)
void gemm_tf32(const float* __restrict__ A, int K,
               const float* __restrict__ W,
               const float* __restrict__ bias,
               float* __restrict__ C, int N,
               float* __restrict__ Cpart, int prec)
{
    int ksplit = gridDim.y;
    int klen = K / ksplit;
    int kstart = blockIdx.y * klen;
    int nblk = blockIdx.x * 128;
    int t = threadIdx.x;
    int r0 = t >> 2;
    int k4 = (t & 3) * 4;
    float* part = (ksplit > 1) ? (Cpart + (size_t)blockIdx.y * 128 * N) : nullptr;
    gemm_body(A + (size_t)r0 * K + kstart + k4,
              A + (size_t)(r0 + 64) * K + kstart + k4,
              W + (size_t)(nblk + r0) * K + kstart + k4,
              W + (size_t)(nblk + r0 + 64) * K + kstart + k4,
              bias, C, N, part, nblk, klen / 16, prec);
}

// fused GRU GEMMs + embedding gather: grid (12, 8, 2)
// z=0: gx = gathered-embeddings[128, 2048] @ W_ih^T  (A staged straight from tables)
// z=1: gh = h[128, 512] @ W_hh^T
__global__ __launch_bounds__(256, 2)
void gemm_gru(const float* __restrict__ hprev,
              const float* __restrict__ W_ih, const float* __restrict__ W_hh,
              const int* __restrict__ seq, const int* __restrict__ pos,
              const int* __restrict__ yr, const int* __restrict__ fr,
              const float* __restrict__ et, const float* __restrict__ ep,
              const float* __restrict__ ey, const float* __restrict__ ei)
{
    int N = 3 * Hq;
    int nblk = blockIdx.x * 128;
    int t = threadIdx.x;
    int r0 = t >> 2;
    int k4 = (t & 3) * 4;
    if (blockIdx.z == 0) {
        int K = 4 * Hq;                 // 2048
        int klen = K / 8;               // 256 -> one table per split
        int kstart = blockIdx.y * klen;
        int region = blockIdx.y >> 1;   // 0:tok 1:pos 2:year 3:inst
        int coff = (blockIdx.y & 1) * 256 + k4;
        const float* tbl; const int* idxa;
        if (region == 0)      { tbl = et; idxa = seq; }
        else if (region == 1) { tbl = ep; idxa = pos; }
        else if (region == 2) { tbl = ey; idxa = yr; }
        else                  { tbl = ei; idxa = fr; }
        const float* a0 = tbl + (size_t)idxa[r0] * Hq + coff;
        const float* a1 = tbl + (size_t)idxa[r0 + 64] * Hq + coff;
        gemm_body(a0, a1,
                  W_ih + (size_t)(nblk + r0) * K + kstart + k4,
                  W_ih + (size_t)(nblk + r0 + 64) * K + kstart + k4,
                  nullptr, nullptr, N,
                  g_gemm_part + (size_t)blockIdx.y * 128 * N,
                  nblk, klen / 16, 3);
    } else {
        int K = Hq;
        int klen = K / 8;               // 64
        int kstart = blockIdx.y * klen;
        gemm_body(hprev + (size_t)r0 * K + kstart + k4,
                  hprev + (size_t)(r0 + 64) * K + kstart + k4,
                  W_hh + (size_t)(nblk + r0) * K + kstart + k4,
                  W_hh + (size_t)(nblk + r0 + 64) * K + kstart + k4,
                  nullptr, nullptr, N,
                  g_gemm_part2 + (size_t)blockIdx.y * 128 * N,
                  nblk, klen / 16, 3);
    }
}

__global__ void reduce_split(const float* __restrict__ part, const float* __restrict__ bias,
                             float* __restrict__ C, int total, int N, int ksplit, int act)
{
    int idx = blockIdx.x * 256 + threadIdx.x;
    if (idx >= total) return;
    float s = 0.f;
    for (int z = 0; z < ksplit; z++) s += part[(size_t)z * total + idx];
    s += bias[idx % N];
    if (act == 1) s = tanhf(s);
    C[idx] = s;
}

// ---------------- fused split-K reduce + GRU gates ----------------
__global__ void gate_fused_kernel(const float* __restrict__ hprev,
                                  const float* __restrict__ b_ih,
                                  const float* __restrict__ b_hh,
                                  float* __restrict__ out_h)
{
    int idx = blockIdx.x * 256 + threadIdx.x;
    int b = idx >> 9;
    int j = idx & 511;
    float xr = 0.f, xz = 0.f, xn = 0.f, hr = 0.f, hz = 0.f, hn = 0.f;
#pragma unroll
    for (int z = 0; z < 8; z++) {
        const float* P0 = g_gemm_part  + ((size_t)z * Bq + b) * (3 * Hq);
        const float* P1 = g_gemm_part2 + ((size_t)z * Bq + b) * (3 * Hq);
        xr += P0[j]; xz += P0[Hq + j]; xn += P0[2 * Hq + j];
        hr += P1[j]; hz += P1[Hq + j]; hn += P1[2 * Hq + j];
    }
    xr += b_ih[j]; xz += b_ih[Hq + j]; xn += b_ih[2 * Hq + j];
    hr += b_hh[j]; hz += b_hh[Hq + j]; hn += b_hh[2 * Hq + j];
    float r = 1.f / (1.f + __expf(-(xr + hr)));
    float z = 1.f / (1.f + __expf(-(xz + hz)));
    float n = tanhf(xn + r * hn);
    float hnew = (1.f - z) * n + z * hprev[idx];
    g_hnew[idx] = hnew;
    g_concat_in[(size_t)b * 2 * Hq + j] = hnew;
    if (out_h) out_h[idx] = hnew;
}

// ---------------- fused attention: single pass over enc ----------------
__global__ __launch_bounds__(128)
void attn_fused_kernel(const float* __restrict__ enc)
{
    int b = blockIdx.y;
    int t = threadIdx.x;
    int w = t >> 5;
    int lane = t & 31;
    int chunk = blockIdx.x * 4 + w;

    const float4* h4 = (const float4*)(g_hnew + (size_t)b * Hq);
    float4 h0 = h4[lane];
    float4 h1 = h4[lane + 32];
    float4 h2 = h4[lane + 64];
    float4 h3 = h4[lane + 96];

    float m = -1e30f, Z = 0.f;
    float4 c0 = make_float4(0.f,0.f,0.f,0.f), c1 = c0, c2 = c0, c3 = c0;

    int sbase = chunk * 64;
#pragma unroll 2
    for (int s0 = 0; s0 < 64; s0++) {
        int s = sbase + s0;
        const float4* e4 = (const float4*)(enc + ((size_t)s * Bq + b) * Hq);
        float4 e0 = e4[lane];
        float4 e1 = e4[lane + 32];
        float4 e2 = e4[lane + 64];
        float4 e3 = e4[lane + 96];
        float dp = e0.x*h0.x + e0.y*h0.y + e0.z*h0.z + e0.w*h0.w
                 + e1.x*h1.x + e1.y*h1.y + e1.z*h1.z + e1.w*h1.w
                 + e2.x*h2.x + e2.y*h2.y + e2.z*h2.z + e2.w*h2.w
                 + e3.x*h3.x + e3.y*h3.y + e3.z*h3.z + e3.w*h3.w;
#pragma unroll
        for (int off = 16; off > 0; off >>= 1)
            dp += __shfl_xor_sync(0xffffffffu, dp, off);
        if (lane == 0) g_scores[(size_t)b * Sq + s] = dp;
        if (dp <= m) {
            float p = __expf(dp - m);
            Z += p;
            c0.x += p*e0.x; c0.y += p*e0.y; c0.z += p*e0.z; c0.w += p*e0.w;
            c1.x += p*e1.x; c1.y += p*e1.y; c1.z += p*e1.z; c1.w += p*e1.w;
            c2.x += p*e2.x; c2.y += p*e2.y; c2.z += p*e2.z; c2.w += p*e2.w;
            c3.x += p*e3.x; c3.y += p*e3.y; c3.z += p*e3.z; c3.w += p*e3.w;
        } else {
            float corr = __expf(m - dp);
            Z = Z * corr + 1.f;
            c0.x = c0.x*corr + e0.x; c0.y = c0.y*corr + e0.y; c0.z = c0.z*corr + e0.z; c0.w = c0.w*corr + e0.w;
            c1.x = c1.x*corr + e1.x; c1.y = c1.y*corr + e1.y; c1.z = c1.z*corr + e1.z; c1.w = c1.w*corr + e1.w;
            c2.x = c2.x*corr + e2.x; c2.y = c2.y*corr + e2.y; c2.z = c2.z*corr + e2.z; c2.w = c2.w*corr + e2.w;
            c3.x = c3.x*corr + e3.x; c3.y = c3.y*corr + e3.y; c3.z = c3.z*corr + e3.z; c3.w = c3.w*corr + e3.w;
            m = dp;
        }
    }

    int pc = b * NCHUNK + chunk;
    float4* pctx = (float4*)(g_pctx + (size_t)pc * Hq);
    pctx[lane]      = c0;
    pctx[lane + 32] = c1;
    pctx[lane + 64] = c2;
    pctx[lane + 96] = c3;
    if (lane == 0) { g_pm[pc] = m; g_pz[pc] = Z; }
}

// ---------------- combine partials -> context + write attn weights ----------------
__global__ __launch_bounds__(128)
void attn_reduce_kernel(float* __restrict__ out_attn)
{
    __shared__ float scale[NCHUNK];
    __shared__ float smax[NCHUNK];
    __shared__ float ssum[NCHUNK];
    __shared__ float sM, sZinv;
    int b = blockIdx.x;
    int t = threadIdx.x;
    if (t < NCHUNK) { smax[t] = g_pm[b * NCHUNK + t]; ssum[t] = g_pz[b * NCHUNK + t]; }
    __syncthreads();
    if (t == 0) {
        float M = -1e30f;
        for (int c = 0; c < NCHUNK; c++) M = fmaxf(M, smax[c]);
        float Zt = 0.f;
        for (int c = 0; c < NCHUNK; c++) {
            float sc = __expf(smax[c] - M);
            scale[c] = sc;
            Zt += ssum[c] * sc;
        }
        sM = M;
        sZinv = 1.f / Zt;
    }
    __syncthreads();
    float zinv = sZinv;
    float M = sM;
    float a0 = 0.f, a1 = 0.f, a2 = 0.f, a3 = 0.f;
    for (int c = 0; c < NCHUNK; c++) {
        const float4 v = *(const float4*)(g_pctx + ((size_t)(b * NCHUNK + c)) * Hq + t * 4);
        float sc = scale[c];
        a0 += v.x * sc; a1 += v.y * sc; a2 += v.z * sc; a3 += v.w * sc;
    }
    float4 r = make_float4(a0 * zinv, a1 * zinv, a2 * zinv, a3 * zinv);
    *(float4*)(g_concat_in + (size_t)b * 2 * Hq + Hq + t * 4) = r;

    if (out_attn) {
        const float* sc_row = g_scores + (size_t)b * Sq;
        float* out_row = out_attn + (size_t)b * Sq;
        for (int i = t; i < Sq; i += 128)
            out_row[i] = __expf(sc_row[i] - M) * zinv;
    }
}

// ---------------- launch ----------------
extern "C" void kernel_launch(void* const* d_in, const int* in_sizes, int n_in,
                              void* d_out, int out_size)
{
    const int* input_seq   = (const int*)d_in[0];
    const int* positions   = (const int*)d_in[1];
    const int* years       = (const int*)d_in[2];
    const int* froms       = (const int*)d_in[3];
    const float* last_h    = (const float*)d_in[4];
    const float* enc       = (const float*)d_in[5];
    const float* emb_tok   = (const float*)d_in[6];
    const float* emb_pos   = (const float*)d_in[7];
    const float* emb_year  = (const float*)d_in[8];
    const float* emb_inst  = (const float*)d_in[9];
    const float* W_ih      = (const float*)d_in[10];
    const float* b_ih      = (const float*)d_in[11];
    const float* W_hh      = (const float*)d_in[12];
    const float* b_hh      = (const float*)d_in[13];
    const float* W_concat  = (const float*)d_in[14];
    const float* b_concat  = (const float*)d_in[15];
    const float* W_out     = (const float*)d_in[16];
    const float* b_out     = (const float*)d_in[17];

    float* out = (float*)d_out;
    float* out_logits = out;
    float* out_h = nullptr;
    float* out_attn = nullptr;
    long long need = (long long)Bq * Vq + (long long)Bq * Hq + (long long)Bq * Sq;
    if ((long long)out_size >= need) {
        out_h = out + (size_t)Bq * Vq;
        out_attn = out_h + (size_t)Bq * Hq;
    }

    float *part, *concat_in, *concat_out;
    cudaGetSymbolAddress((void**)&part, g_gemm_part);
    cudaGetSymbolAddress((void**)&concat_in, g_concat_in);
    cudaGetSymbolAddress((void**)&concat_out, g_concat_out);

    cudaFuncSetAttribute(gemm_tf32, cudaFuncAttributeMaxDynamicSharedMemorySize, GEMM_SMEM_BYTES);
    cudaFuncSetAttribute(gemm_gru, cudaFuncAttributeMaxDynamicSharedMemorySize, GEMM_SMEM_BYTES);

    // 1. gx (embedding gather fused) AND gh in one launch (split-K 8, tf32x3)
    gemm_gru<<<dim3(12, 8, 2), 256, GEMM_SMEM_BYTES>>>(last_h, W_ih, W_hh,
        input_seq, positions, years, froms, emb_tok, emb_pos, emb_year, emb_inst);
    // 2. fused split-K reduce + gates -> h_new
    gate_fused_kernel<<<(Bq * Hq) / 256, 256>>>(last_h, b_ih, b_hh, out_h);
    // 3. fused scores + online-softmax context (single pass over enc)
    attn_fused_kernel<<<dim3(16, Bq), 128>>>(enc);
    // 4. combine partials -> context + attn weights output
    attn_reduce_kernel<<<Bq, 128>>>(out_attn);
    // 5. concat_out = tanh(concat_in @ W_concat^T + b_concat) (tf32x3, split-K 8)
    gemm_tf32<<<dim3(4, 8), 256, GEMM_SMEM_BYTES>>>(concat_in, 2 * Hq, W_concat, nullptr, nullptr, Hq, part, 3);
    reduce_split<<<(Bq * Hq + 255) / 256, 256>>>(part, b_concat, concat_out, Bq * Hq, Hq, 8, 1);
    // 6. logits = concat_out @ W_out^T + b_out  (tf32x2, split-K 1, direct out)
    gemm_tf32<<<dim3(Vq / 128, 1), 256, GEMM_SMEM_BYTES>>>(concat_out, Hq, W_out, b_out, out_logits, Vq, nullptr, 2);
}